// round 13
// baseline (speedup 1.0000x reference)
#include <cuda_runtime.h>
#include <cuda_fp16.h>
#include <cstdint>
#include <cstddef>
#include <math.h>
#include <float.h>

#define NG   32
#define PTS  1024
#define NPT  (NG*PTS)      // 32768
#define KNB  30
#define DIM  64
#define GCH  8             // graphs per dist/topk chunk (32MB dist slab, L2-resident)

// ---------------- device scratch (static, no allocations) ----------------
__device__ float g_s[NPT];
__device__ int   g_idx[NPT*KNB];
__device__ float g_B[NPT*DIM];
__device__ float g_C[NPT*DIM];
__device__ float g_hcat[NPT*192];
__device__ float g_big[(size_t)NPT*1024];   // dist matrix; later a1h/a1l split buffers
__device__ float g_h1[NPT*256];             // later a2h/a2l
__device__ float g_h2[NPT*128];             // later a3h/a3l
__device__ unsigned g_w2h[64*32];
__device__ unsigned g_w2l[64*32];
__device__ unsigned g_x1h[NPT*8],  g_x1l[NPT*8];
__device__ unsigned g_ah0[NPT*96], g_al0[NPT*96];
__device__ unsigned g_wlh[1024*96],  g_wll[1024*96];
__device__ unsigned g_hw1h[256*512], g_hw1l[256*512];
__device__ unsigned g_hw2h[128*128], g_hw2l[128*128];
__device__ unsigned g_hw3h[64*64],   g_hw3l[64*64];

// ---------------- fp16 split helpers ----------------
__device__ __forceinline__ void split2(float x, float y, unsigned& h, unsigned& l) {
    __half2 p = __floats2half2_rn(x, y);
    h = *reinterpret_cast<unsigned*>(&p);
    float rx = x - __low2float(p);
    float ry = y - __high2float(p);
    __half2 q = __floats2half2_rn(rx, ry);
    l = *reinterpret_cast<unsigned*>(&q);
}

#define MMA_F16(d, a0,a1,a2,a3, b0,b1) \
    asm volatile("mma.sync.aligned.m16n8k16.row.col.f32.f16.f16.f32 " \
        "{%0,%1,%2,%3}, {%4,%5,%6,%7}, {%8,%9}, {%0,%1,%2,%3};" \
        : "+f"(d[0]),"+f"(d[1]),"+f"(d[2]),"+f"(d[3]) \
        : "r"(a0),"r"(a1),"r"(a2),"r"(a3), "r"(b0),"r"(b1))

// ---------------- prep kernels ----------------
__global__ void splitx1_k(const float* __restrict__ x) {
    int e = blockIdx.x*256 + threadIdx.x;
    int i = e >> 3, p = e & 7;
    float v0 = 0.f, v1 = 0.f;
    if (p < 7) { v0 = x[i*14 + 2*p]; v1 = x[i*14 + 2*p + 1]; }
    unsigned h, l; split2(v0, v1, h, l);
    g_x1h[e] = h; g_x1l[e] = l;
}

// coalesced transpose-split: W [K][N] fp32 -> Wh/Wl [N][KP] fp16-pair words.
// 32x32 tiles through smem; 256 threads, each handles 4 tile rows.
__global__ void wprep_k(const float* __restrict__ W, unsigned* __restrict__ Wh,
                        unsigned* __restrict__ Wl, int K, int N) {
    __shared__ unsigned th[32][33], tl[32][33];
    int KP = K >> 1;
    int tp0 = blockIdx.x*32, tn0 = blockIdx.y*32;
    int tx = threadIdx.x & 31, ty4 = (threadIdx.x >> 5)*4;
    #pragma unroll
    for (int q = 0; q < 4; q++) {
        int p = tp0 + ty4 + q;               // pair index (row pair 2p,2p+1)
        float w0 = W[(size_t)(2*p)*N + tn0 + tx];
        float w1 = W[(size_t)(2*p + 1)*N + tn0 + tx];
        unsigned h, l; split2(w0, w1, h, l);
        th[ty4 + q][tx] = h;
        tl[ty4 + q][tx] = l;
    }
    __syncthreads();
    #pragma unroll
    for (int q = 0; q < 4; q++) {
        int n = tn0 + ty4 + q;
        Wh[(size_t)n*KP + tp0 + tx] = th[tx][ty4 + q];
        Wl[(size_t)n*KP + tp0 + tx] = tl[tx][ty4 + q];
    }
}

// ---------------- pairwise distances (pre-split fp16 3-term mma) ----------------
template<int F>
__global__ void __launch_bounds__(256, 2) distmma_k(
        const unsigned* __restrict__ Xh, const unsigned* __restrict__ Xl,
        int strideP, int offP, int goff) {
    constexpr int PAIRS = ((F + 15)/16)*8;
    constexpr int STR   = PAIRS + 4;
    __shared__ unsigned Ah[128*STR], Al[128*STR];
    __shared__ unsigned Bh[64*STR],  Bl[64*STR];
    int g  = blockIdx.z + goff;
    int bm = blockIdx.y*128, bn = blockIdx.x*64;
    int tid = threadIdx.x, lane = tid & 31, warp = tid >> 5;
    int wm = warp & 3, wn = warp >> 2;
    int gid = lane >> 2, tig = lane & 3;
    int base = g*PTS;

    for (int e = tid; e < 32*PAIRS; e += 256) {
        int r = e / (PAIRS/4), c4 = (e % (PAIRS/4))*4;
        size_t go = (size_t)(base + bm + r)*strideP + offP + c4;
        *(uint4*)&Ah[r*STR + c4] = *(const uint4*)&Xh[go];
        *(uint4*)&Al[r*STR + c4] = *(const uint4*)&Xl[go];
    }
    for (int e = tid; e < 16*PAIRS; e += 256) {
        int r = e / (PAIRS/4), c4 = (e % (PAIRS/4))*4;
        size_t go = (size_t)(base + bn + r)*strideP + offP + c4;
        *(uint4*)&Bh[r*STR + c4] = *(const uint4*)&Xh[go];
        *(uint4*)&Bl[r*STR + c4] = *(const uint4*)&Xl[go];
    }
    __syncthreads();

    float acc[2][4][4] = {};
    #pragma unroll
    for (int s = 0; s < PAIRS/8; s++) {
        int p = s*8 + tig;
        unsigned ah[2][4], al[2][4];
        #pragma unroll
        for (int mi = 0; mi < 2; mi++) {
            int r = wm*32 + mi*16 + gid;
            ah[mi][0] = Ah[r*STR + p];       ah[mi][1] = Ah[(r+8)*STR + p];
            ah[mi][2] = Ah[r*STR + p + 4];   ah[mi][3] = Ah[(r+8)*STR + p + 4];
            al[mi][0] = Al[r*STR + p];       al[mi][1] = Al[(r+8)*STR + p];
            al[mi][2] = Al[r*STR + p + 4];   al[mi][3] = Al[(r+8)*STR + p + 4];
        }
        #pragma unroll
        for (int ni = 0; ni < 4; ni++) {
            int c = wn*32 + ni*8 + gid;
            unsigned bh0 = Bh[c*STR + p], bh1 = Bh[c*STR + p + 4];
            unsigned bl0 = Bl[c*STR + p], bl1 = Bl[c*STR + p + 4];
            #pragma unroll
            for (int mi = 0; mi < 2; mi++) {
                MMA_F16(acc[mi][ni], ah[mi][0],ah[mi][1],ah[mi][2],ah[mi][3], bh0,bh1);
                MMA_F16(acc[mi][ni], ah[mi][0],ah[mi][1],ah[mi][2],ah[mi][3], bl0,bl1);
                MMA_F16(acc[mi][ni], al[mi][0],al[mi][1],al[mi][2],al[mi][3], bh0,bh1);
            }
        }
    }
    #pragma unroll
    for (int mi = 0; mi < 2; mi++) {
        int row = bm + wm*32 + mi*16 + gid;
        float si0 = g_s[base + row];
        float si1 = g_s[base + row + 8];
        #pragma unroll
        for (int ni = 0; ni < 4; ni++) {
            int col = bn + wn*32 + ni*8 + 2*tig;
            float sj0 = g_s[base + col];
            float sj1 = g_s[base + col + 1];
            float2 o0 = make_float2(si0 + sj0 - 2.f*acc[mi][ni][0],
                                    si0 + sj1 - 2.f*acc[mi][ni][1]);
            float2 o1 = make_float2(si1 + sj0 - 2.f*acc[mi][ni][2],
                                    si1 + sj1 - 2.f*acc[mi][ni][3]);
            *(float2*)&g_big[(size_t)(base + row)*PTS + col]     = o0;
            *(float2*)&g_big[(size_t)(base + row + 8)*PTS + col] = o1;
        }
    }
}

// ---------------- top-K selection (REDUX min + top-2 cache; exact) ----------------
__global__ void topk_k(int ioff) {
    int w = threadIdx.x >> 5, lane = threadIdx.x & 31;
    int i = ioff + blockIdx.x*8 + w;
    int g = i >> 10;
    const float* row = &g_big[(size_t)i*PTS];
    unsigned dl[32];
    #pragma unroll
    for (int t = 0; t < 32; t++) {
        int b = __float_as_int(row[lane + 32*t]);
        dl[t] = (unsigned)b ^ (0x80000000u | (unsigned)(b >> 31));
    }
    unsigned m1 = 0xFFFFFFFFu, m2 = 0xFFFFFFFFu; int t1 = 0, t2 = 0;
    #pragma unroll
    for (int t = 0; t < 32; t++) {
        unsigned v = dl[t];
        if (v < m1) { m2 = m1; t2 = t1; m1 = v; t1 = t; }
        else if (v < m2) { m2 = v; t2 = t; }
    }
    bool have2 = true;
    for (int kk = 0; kk < KNB; kk++) {
        unsigned umin = __reduce_min_sync(0xffffffffu, m1);
        unsigned myjv = (m1 == umin) ? (unsigned)(lane + 32*t1) : 0xFFFFFFFFu;
        unsigned jv = __reduce_min_sync(0xffffffffu, myjv);
        if (lane == 0) g_idx[(size_t)i*KNB + kk] = (g << 10) + (int)jv;
        if ((jv & 31) == lane) {
            int rt = (int)(jv >> 5);
            #pragma unroll
            for (int t = 0; t < 32; t++) if (t == rt) dl[t] = 0xFFFFFFFFu;
            if (have2) { m1 = m2; t1 = t2; have2 = false; }
            else {
                m1 = 0xFFFFFFFFu; m2 = 0xFFFFFFFFu; t1 = 0; t2 = 0;
                #pragma unroll
                for (int t = 0; t < 32; t++) {
                    unsigned vv = dl[t];
                    if (vv < m1) { m2 = m1; t2 = t1; m1 = vv; t1 = t; }
                    else if (vv < m2) { m2 = vv; t2 = t; }
                }
                have2 = true;
            }
        }
    }
}

// ---------------- precompute B/C (+ squared norms fused) ----------------
template<int F>
__global__ void precompute_k(const float* __restrict__ x, int ldx,
                             const float* __restrict__ W1, const float* __restrict__ b1) {
    int gid = blockIdx.x*256 + threadIdx.x;
    int i = gid >> 6, c = gid & 63;
    const float* xr = x + (size_t)i*ldx;
    float a = 0.f, b = 0.f, s = 0.f;
    #pragma unroll
    for (int f = 0; f < F; f++) {
        float xv = xr[f];
        a += xv * W1[f*DIM + c];
        b += xv * W1[(F + f)*DIM + c];
        s += xv * xv;
    }
    g_B[gid] = b;
    g_C[gid] = a - b + b1[c];
    if (c == 0) g_s[i] = s;
}

// ---------------- edgeconv W2 prep ----------------
__global__ void w2prep_k(const float* __restrict__ W2) {
    int e = blockIdx.x*256 + threadIdx.x;
    int n = e & 63, j = e >> 6;
    float w0 = W2[(2*j)*64 + n];
    float w1 = W2[(2*j+1)*64 + n];
    unsigned h, l; split2(w0, w1, h, l);
    g_w2h[n*32 + j] = h;
    g_w2l[n*32 + j] = l;
}

// ---------------- edgeconv ----------------
template<bool AL, bool SPLITLO>
__global__ void __launch_bounds__(128) edgeconv_k(
        const float* __restrict__ b2, float* __restrict__ out, int ldo,
        unsigned* __restrict__ oh, unsigned* __restrict__ ol) {
    __shared__ unsigned Hh[4][32][36];
    __shared__ unsigned Hl[4][32][36];
    int tid = threadIdx.x, lane = tid & 31, warp = tid >> 5;
    int gid = lane >> 2, tig = lane & 3;
    int i = blockIdx.x*4 + warp;

    unsigned (*hh)[36] = Hh[warp];
    unsigned (*hl)[36] = Hl[warp];
    const int* idxr = g_idx + (size_t)i*KNB;
    float2 cv = *(const float2*)&g_C[(size_t)i*DIM + 2*lane];
    #pragma unroll
    for (int k = 0; k < 32; k++) {
        int j = idxr[(k < KNB) ? k : 0];
        float2 bv = *(const float2*)&g_B[(size_t)j*DIM + 2*lane];
        float f0 = fmaxf(cv.x + bv.x, 0.f);
        float f1 = fmaxf(cv.y + bv.y, 0.f);
        unsigned h, l; split2(f0, f1, h, l);
        hh[k][lane] = h;
        if (AL) hl[k][lane] = l;
    }
    __syncwarp();

    float acc[2][8][4] = {};
    #pragma unroll
    for (int s = 0; s < 4; s++) {
        int p = s*8 + tig;
        unsigned ah[2][4], al[2][4];
        #pragma unroll
        for (int mi = 0; mi < 2; mi++) {
            int r = mi*16 + gid;
            ah[mi][0] = hh[r][p];   ah[mi][1] = hh[r+8][p];
            ah[mi][2] = hh[r][p+4]; ah[mi][3] = hh[r+8][p+4];
            if (AL) {
                al[mi][0] = hl[r][p];   al[mi][1] = hl[r+8][p];
                al[mi][2] = hl[r][p+4]; al[mi][3] = hl[r+8][p+4];
            }
        }
        #pragma unroll
        for (int ni = 0; ni < 8; ni++) {
            int c = ni*8 + gid;
            unsigned bh0 = g_w2h[c*32 + p], bh1 = g_w2h[c*32 + p + 4];
            unsigned bl0 = g_w2l[c*32 + p], bl1 = g_w2l[c*32 + p + 4];
            #pragma unroll
            for (int mi = 0; mi < 2; mi++) {
                MMA_F16(acc[mi][ni], ah[mi][0],ah[mi][1],ah[mi][2],ah[mi][3], bh0,bh1);
                MMA_F16(acc[mi][ni], ah[mi][0],ah[mi][1],ah[mi][2],ah[mi][3], bl0,bl1);
                if (AL)
                    MMA_F16(acc[mi][ni], al[mi][0],al[mi][1],al[mi][2],al[mi][3], bh0,bh1);
            }
        }
    }
    #pragma unroll
    for (int ni = 0; ni < 8; ni++) {
        float m0 = fmaxf(fmaxf(acc[0][ni][0], acc[0][ni][2]),
                         fmaxf(acc[1][ni][0], acc[1][ni][2]));
        float m1 = fmaxf(fmaxf(acc[0][ni][1], acc[0][ni][3]),
                         fmaxf(acc[1][ni][1], acc[1][ni][3]));
        m0 = fmaxf(m0, __shfl_xor_sync(0xffffffffu, m0, 4));
        m1 = fmaxf(m1, __shfl_xor_sync(0xffffffffu, m1, 4));
        m0 = fmaxf(m0, __shfl_xor_sync(0xffffffffu, m0, 8));
        m1 = fmaxf(m1, __shfl_xor_sync(0xffffffffu, m1, 8));
        m0 = fmaxf(m0, __shfl_xor_sync(0xffffffffu, m0, 16));
        m1 = fmaxf(m1, __shfl_xor_sync(0xffffffffu, m1, 16));
        if (gid == 0) {
            int col = ni*8 + tig*2;
            float2 bz = *(const float2*)&b2[col];
            float o0 = fmaxf(m0 + bz.x, 0.f);
            float o1 = fmaxf(m1 + bz.y, 0.f);
            *(float2*)&out[(size_t)i*ldo + col] = make_float2(o0, o1);
            unsigned h, l; split2(o0, o1, h, l);
            oh[(size_t)i*96 + (col >> 1)] = h;
            if (SPLITLO) ol[(size_t)i*96 + (col >> 1)] = l;
        }
    }
}

// ---------------- wide-M pre-split GEMM with internal N loop ----------------
template<bool SPLITLO, int NT>
__global__ void __launch_bounds__(256, 2) hgemm_w(
        const unsigned* __restrict__ Ah_g,
        const unsigned* __restrict__ Wh_g, const unsigned* __restrict__ Wl_g,
        const float* __restrict__ bias,
        unsigned* __restrict__ Oh, unsigned* __restrict__ Ol,
        int KP, int Nd) {
    __shared__ unsigned Ahs[256*20];
    __shared__ unsigned Bhs[64*20], Bls[64*20];
    int tid  = threadIdx.x;
    int lane = tid & 31, warp = tid >> 5;
    int wm = warp & 3, wn = warp >> 2;
    int gid = lane >> 2, tig = lane & 3;
    int bm = blockIdx.y * 256;
    int NdP = Nd >> 1;

    #pragma unroll 1
    for (int nt = 0; nt < NT; nt++) {
        int bn = (blockIdx.x*NT + nt)*64;
        float acc[4][4][4] = {};
        #pragma unroll 1
        for (int k0p = 0; k0p < KP; k0p += 16) {
            uint4 ra[4], rbh, rbl;
            #pragma unroll
            for (int q = 0; q < 4; q++) {
                int e = q*256 + tid;
                int r = e >> 2, c4 = (e & 3)*4;
                ra[q] = *(const uint4*)&Ah_g[(size_t)(bm + r)*KP + k0p + c4];
            }
            {
                int r = tid >> 2, c4 = (tid & 3)*4;
                size_t go = (size_t)(bn + r)*KP + k0p + c4;
                rbh = *(const uint4*)&Wh_g[go];
                rbl = *(const uint4*)&Wl_g[go];
            }
            __syncthreads();
            #pragma unroll
            for (int q = 0; q < 4; q++) {
                int e = q*256 + tid;
                int r = e >> 2, c4 = (e & 3)*4;
                *(uint4*)&Ahs[r*20 + c4] = ra[q];
            }
            {
                int r = tid >> 2, c4 = (tid & 3)*4;
                *(uint4*)&Bhs[r*20 + c4] = rbh;
                *(uint4*)&Bls[r*20 + c4] = rbl;
            }
            __syncthreads();
            #pragma unroll
            for (int s = 0; s < 2; s++) {
                int p = s*8 + tig;
                unsigned ah[4][4];
                #pragma unroll
                for (int mi = 0; mi < 4; mi++) {
                    int r = wm*64 + mi*16 + gid;
                    ah[mi][0] = Ahs[r*20 + p];       ah[mi][1] = Ahs[(r+8)*20 + p];
                    ah[mi][2] = Ahs[r*20 + p + 4];   ah[mi][3] = Ahs[(r+8)*20 + p + 4];
                }
                #pragma unroll
                for (int ni = 0; ni < 4; ni++) {
                    int c = wn*32 + ni*8 + gid;
                    unsigned bh0 = Bhs[c*20 + p], bh1 = Bhs[c*20 + p + 4];
                    unsigned bl0 = Bls[c*20 + p], bl1 = Bls[c*20 + p + 4];
                    #pragma unroll
                    for (int mi = 0; mi < 4; mi++) {
                        MMA_F16(acc[mi][ni], ah[mi][0],ah[mi][1],ah[mi][2],ah[mi][3], bh0,bh1);
                        MMA_F16(acc[mi][ni], ah[mi][0],ah[mi][1],ah[mi][2],ah[mi][3], bl0,bl1);
                    }
                }
            }
        }
        #pragma unroll
        for (int mi = 0; mi < 4; mi++) {
            int row = bm + wm*64 + mi*16 + gid;
            #pragma unroll
            for (int ni = 0; ni < 4; ni++) {
                int col = bn + wn*32 + ni*8 + tig*2;
                float bz0 = bias[col], bz1 = bias[col+1];
                float z0 = fmaxf(acc[mi][ni][0] + bz0, 0.f);
                float z1 = fmaxf(acc[mi][ni][1] + bz1, 0.f);
                float z2 = fmaxf(acc[mi][ni][2] + bz0, 0.f);
                float z3 = fmaxf(acc[mi][ni][3] + bz1, 0.f);
                unsigned h, l;
                split2(z0, z1, h, l);
                Oh[(size_t)row*NdP + (col >> 1)] = h;
                if (SPLITLO) Ol[(size_t)row*NdP + (col >> 1)] = l;
                split2(z2, z3, h, l);
                Oh[(size_t)(row+8)*NdP + (col >> 1)] = h;
                if (SPLITLO) Ol[(size_t)(row+8)*NdP + (col >> 1)] = l;
            }
        }
    }
}

// ---------------- pre-split fp16 GEMM (3-term, small layers) ----------------
template<bool RELU, bool SPLITOUT>
__global__ void __launch_bounds__(256, 2) hgemm_ps(
        const unsigned* __restrict__ Ah_g, const unsigned* __restrict__ Al_g,
        const unsigned* __restrict__ Wh_g, const unsigned* __restrict__ Wl_g,
        const float* __restrict__ bias,
        unsigned* __restrict__ Oh, unsigned* __restrict__ Ol,
        float* __restrict__ Of, int KP, int Nd) {
    __shared__ unsigned Ahs[128*20], Als[128*20];
    __shared__ unsigned Bhs[64*20],  Bls[64*20];
    int tid  = threadIdx.x;
    int lane = tid & 31, warp = tid >> 5;
    int wm = warp & 3, wn = warp >> 2;
    int gid = lane >> 2, tig = lane & 3;
    int bm = blockIdx.y * 128, bn = blockIdx.x * 64;
    float acc[2][4][4] = {};

    for (int k0p = 0; k0p < KP; k0p += 16) {
        uint4 rah[2], ral[2], rbh, rbl;
        #pragma unroll
        for (int q = 0; q < 2; q++) {
            int e = q*256 + tid;
            int r = e >> 2, c4 = (e & 3)*4;
            size_t go = (size_t)(bm + r)*KP + k0p + c4;
            rah[q] = *(const uint4*)&Ah_g[go];
            ral[q] = *(const uint4*)&Al_g[go];
        }
        {
            int r = tid >> 2, c4 = (tid & 3)*4;
            size_t go = (size_t)(bn + r)*KP + k0p + c4;
            rbh = *(const uint4*)&Wh_g[go];
            rbl = *(const uint4*)&Wl_g[go];
        }
        __syncthreads();
        #pragma unroll
        for (int q = 0; q < 2; q++) {
            int e = q*256 + tid;
            int r = e >> 2, c4 = (e & 3)*4;
            *(uint4*)&Ahs[r*20 + c4] = rah[q];
            *(uint4*)&Als[r*20 + c4] = ral[q];
        }
        {
            int r = tid >> 2, c4 = (tid & 3)*4;
            *(uint4*)&Bhs[r*20 + c4] = rbh;
            *(uint4*)&Bls[r*20 + c4] = rbl;
        }
        __syncthreads();
        #pragma unroll
        for (int s = 0; s < 2; s++) {
            int p = s*8 + tig;
            unsigned ah[2][4], al[2][4];
            #pragma unroll
            for (int mi = 0; mi < 2; mi++) {
                int r = wm*32 + mi*16 + gid;
                ah[mi][0] = Ahs[r*20 + p];       ah[mi][1] = Ahs[(r+8)*20 + p];
                ah[mi][2] = Ahs[r*20 + p + 4];   ah[mi][3] = Ahs[(r+8)*20 + p + 4];
                al[mi][0] = Als[r*20 + p];       al[mi][1] = Als[(r+8)*20 + p];
                al[mi][2] = Als[r*20 + p + 4];   al[mi][3] = Als[(r+8)*20 + p + 4];
            }
            #pragma unroll
            for (int ni = 0; ni < 4; ni++) {
                int c = wn*32 + ni*8 + gid;
                unsigned bh0 = Bhs[c*20 + p], bh1 = Bhs[c*20 + p + 4];
                unsigned bl0 = Bls[c*20 + p], bl1 = Bls[c*20 + p + 4];
                #pragma unroll
                for (int mi = 0; mi < 2; mi++) {
                    MMA_F16(acc[mi][ni], ah[mi][0],ah[mi][1],ah[mi][2],ah[mi][3], bh0,bh1);
                    MMA_F16(acc[mi][ni], ah[mi][0],ah[mi][1],ah[mi][2],ah[mi][3], bl0,bl1);
                    MMA_F16(acc[mi][ni], al[mi][0],al[mi][1],al[mi][2],al[mi][3], bh0,bh1);
                }
            }
        }
    }
    int NdP = Nd >> 1;
    #pragma unroll
    for (int mi = 0; mi < 2; mi++) {
        int row = bm + wm*32 + mi*16 + gid;
        #pragma unroll
        for (int ni = 0; ni < 4; ni++) {
            int col = bn + wn*32 + ni*8 + tig*2;
            float bz0 = bias[col], bz1 = bias[col+1];
            float z0 = acc[mi][ni][0] + bz0;
            float z1 = acc[mi][ni][1] + bz1;
            float z2 = acc[mi][ni][2] + bz0;
            float z3 = acc[mi][ni][3] + bz1;
            if (RELU) {
                z0 = fmaxf(z0, 0.f); z1 = fmaxf(z1, 0.f);
                z2 = fmaxf(z2, 0.f); z3 = fmaxf(z3, 0.f);
            }
            if (SPLITOUT) {
                unsigned h, l;
                split2(z0, z1, h, l);
                Oh[(size_t)row*NdP + (col >> 1)] = h;
                Ol[(size_t)row*NdP + (col >> 1)] = l;
                split2(z2, z3, h, l);
                Oh[(size_t)(row+8)*NdP + (col >> 1)] = h;
                Ol[(size_t)(row+8)*NdP + (col >> 1)] = l;
            } else {
                *(float2*)&Of[(size_t)row*Nd + col]     = make_float2(z0, z1);
                *(float2*)&Of[(size_t)(row+8)*Nd + col] = make_float2(z2, z3);
            }
        }
    }
}

// ---------------- host orchestration ----------------
// dist+topk interleaved per GCH-graph chunk: the 32MB distance slab stays
// L2-resident between producer and consumer.
template<int F, bool EAL>
static void run_conv(const float* xp, int ldx,
                     const unsigned* xh, const unsigned* xl, int strideP, int offP,
                     const float* w1, const float* b1,
                     const float* w2, const float* b2,
                     float* outp, unsigned* oh, unsigned* ol) {
    precompute_k<F><<<(NPT*DIM)/256, 256>>>(xp, ldx, w1, b1);
    for (int q = 0; q < NG/GCH; q++) {
        distmma_k<F><<<dim3(PTS/64, PTS/128, GCH), 256>>>(xh, xl, strideP, offP, q*GCH);
        topk_k<<<GCH*PTS/8, 256>>>(q*GCH*PTS);
    }
    w2prep_k<<<8, 256>>>(w2);
    edgeconv_k<EAL, EAL><<<NPT/4, 128>>>(b2, outp, 192, oh, ol);
}

extern "C" void kernel_launch(void* const* d_in, const int* in_sizes, int n_in,
                              void* d_out, int out_size) {
    const float* x    = (const float*)d_in[0];
    const float* c1w1 = (const float*)d_in[2];
    const float* c1b1 = (const float*)d_in[3];
    const float* c1w2 = (const float*)d_in[4];
    const float* c1b2 = (const float*)d_in[5];
    const float* c2w1 = (const float*)d_in[6];
    const float* c2b1 = (const float*)d_in[7];
    const float* c2w2 = (const float*)d_in[8];
    const float* c2b2 = (const float*)d_in[9];
    const float* c3w1 = (const float*)d_in[10];
    const float* c3b1 = (const float*)d_in[11];
    const float* c3w2 = (const float*)d_in[12];
    const float* c3b2 = (const float*)d_in[13];
    const float* lw   = (const float*)d_in[14];
    const float* lb   = (const float*)d_in[15];
    const float* hw1  = (const float*)d_in[16];
    const float* hb1  = (const float*)d_in[17];
    const float* hw2  = (const float*)d_in[18];
    const float* hb2  = (const float*)d_in[19];
    const float* hw3  = (const float*)d_in[20];
    const float* hb3  = (const float*)d_in[21];
    float* out = (float*)d_out;

    float *hcat, *big, *h1b, *h2b;
    unsigned *x1h, *x1l, *ah0, *al0;
    unsigned *wlh, *wll, *w1h, *w1l, *w2h, *w2l, *w3h, *w3l;
    cudaGetSymbolAddress((void**)&hcat, g_hcat);
    cudaGetSymbolAddress((void**)&big,  g_big);
    cudaGetSymbolAddress((void**)&h1b,  g_h1);
    cudaGetSymbolAddress((void**)&h2b,  g_h2);
    cudaGetSymbolAddress((void**)&x1h,  g_x1h);
    cudaGetSymbolAddress((void**)&x1l,  g_x1l);
    cudaGetSymbolAddress((void**)&ah0,  g_ah0);
    cudaGetSymbolAddress((void**)&al0,  g_al0);
    cudaGetSymbolAddress((void**)&wlh,  g_wlh);
    cudaGetSymbolAddress((void**)&wll,  g_wll);
    cudaGetSymbolAddress((void**)&w1h,  g_hw1h);
    cudaGetSymbolAddress((void**)&w1l,  g_hw1l);
    cudaGetSymbolAddress((void**)&w2h,  g_hw2h);
    cudaGetSymbolAddress((void**)&w2l,  g_hw2l);
    cudaGetSymbolAddress((void**)&w3h,  g_hw3h);
    cudaGetSymbolAddress((void**)&w3l,  g_hw3l);

    unsigned* a1h = (unsigned*)big;  unsigned* a1l = a1h + (size_t)NPT*512;
    unsigned* a2h = (unsigned*)h1b;  unsigned* a2l = a2h + (size_t)NPT*128;
    unsigned* a3h = (unsigned*)h2b;  unsigned* a3l = a3h + (size_t)NPT*64;

    splitx1_k<<<(NPT*8)/256, 256>>>(x);

    run_conv<14, true >(x,         14,  x1h, x1l, 8,  0,  c1w1, c1b1, c1w2, c1b2,
                        hcat,       ah0,      al0);
    run_conv<64, true >(hcat,      192, ah0, al0, 96, 0,  c2w1, c2b1, c2w2, c2b2,
                        hcat + 64,  ah0 + 32, al0 + 32);
    run_conv<64, false>(hcat + 64, 192, ah0, al0, 96, 32, c3w1, c3b1, c3w2, c3b2,
                        hcat + 128, ah0 + 64, al0 + 64);

    // coalesced weight prep (32x32 smem transpose tiles)
    wprep_k<<<dim3(96/32,  1024/32), 256>>>(lw,  wlh, wll, 192,  1024);
    wprep_k<<<dim3(512/32, 256/32),  256>>>(hw1, w1h, w1l, 1024, 256);
    wprep_k<<<dim3(128/32, 128/32),  256>>>(hw2, w2h, w2l, 256,  128);
    wprep_k<<<dim3(64/32,  64/32),   256>>>(hw3, w3h, w3l, 128,  64);

    hgemm_w<false, 4><<<dim3(4, 128), 256>>>(ah0, wlh, wll, lb,  a1h, nullptr, 96,  1024);
    hgemm_w<true,  2><<<dim3(2, 128), 256>>>(a1h, w1h, w1l, hb1, a2h, a2l,     512, 256);
    hgemm_ps<true,  true ><<<dim3(2, 256), 256>>>(a2h, a2l, w2h, w2l, hb2, a3h, a3l, nullptr, 128, 128);
    hgemm_ps<false, false><<<dim3(1, 256), 256>>>(a3h, a3l, w3h, w3l, hb3, nullptr, nullptr, out, 64, 64);
}

// round 14
// speedup vs baseline: 1.1003x; 1.1003x over previous
#include <cuda_runtime.h>
#include <cuda_fp16.h>
#include <cstdint>
#include <cstddef>
#include <math.h>
#include <float.h>

#define NG   32
#define PTS  1024
#define NPT  (NG*PTS)      // 32768
#define KNB  30
#define DIM  64

// ---------------- device scratch (static, no allocations) ----------------
__device__ float g_s[NPT];
__device__ int   g_idx[NPT*KNB];
__device__ float g_B[NPT*DIM];
__device__ float g_C[NPT*DIM];
__device__ float g_hcat[NPT*192];
__device__ float g_big[(size_t)NPT*1024];   // dist matrix; later a1h/a1l split buffers
__device__ float g_h1[NPT*256];             // later a2h/a2l
__device__ float g_h2[NPT*128];             // later a3h/a3l
__device__ unsigned g_w2h[64*32];
__device__ unsigned g_w2l[64*32];
__device__ unsigned g_x1h[NPT*8],  g_x1l[NPT*8];
__device__ unsigned g_ah0[NPT*96], g_al0[NPT*96];
__device__ unsigned g_wlh[1024*96],  g_wll[1024*96];
__device__ unsigned g_hw1h[256*512], g_hw1l[256*512];
__device__ unsigned g_hw2h[128*128], g_hw2l[128*128];
__device__ unsigned g_hw3h[64*64],   g_hw3l[64*64];

// ---------------- fp16 split helpers ----------------
__device__ __forceinline__ void split2(float x, float y, unsigned& h, unsigned& l) {
    __half2 p = __floats2half2_rn(x, y);
    h = *reinterpret_cast<unsigned*>(&p);
    float rx = x - __low2float(p);
    float ry = y - __high2float(p);
    __half2 q = __floats2half2_rn(rx, ry);
    l = *reinterpret_cast<unsigned*>(&q);
}

#define MMA_F16(d, a0,a1,a2,a3, b0,b1) \
    asm volatile("mma.sync.aligned.m16n8k16.row.col.f32.f16.f16.f32 " \
        "{%0,%1,%2,%3}, {%4,%5,%6,%7}, {%8,%9}, {%0,%1,%2,%3};" \
        : "+f"(d[0]),"+f"(d[1]),"+f"(d[2]),"+f"(d[3]) \
        : "r"(a0),"r"(a1),"r"(a2),"r"(a3), "r"(b0),"r"(b1))

// ---------------- prep kernels ----------------
__global__ void splitx1_k(const float* __restrict__ x) {
    int e = blockIdx.x*256 + threadIdx.x;
    int i = e >> 3, p = e & 7;
    float v0 = 0.f, v1 = 0.f;
    if (p < 7) { v0 = x[i*14 + 2*p]; v1 = x[i*14 + 2*p + 1]; }
    unsigned h, l; split2(v0, v1, h, l);
    g_x1h[e] = h; g_x1l[e] = l;
}

// coalesced transpose-split: W [K][N] fp32 -> Wh/Wl [N][KP] fp16-pair words.
__global__ void wprep_k(const float* __restrict__ W, unsigned* __restrict__ Wh,
                        unsigned* __restrict__ Wl, int K, int N) {
    __shared__ unsigned th[32][33], tl[32][33];
    int KP = K >> 1;
    int tp0 = blockIdx.x*32, tn0 = blockIdx.y*32;
    int tx = threadIdx.x & 31, ty4 = (threadIdx.x >> 5)*4;
    #pragma unroll
    for (int q = 0; q < 4; q++) {
        int p = tp0 + ty4 + q;
        float w0 = W[(size_t)(2*p)*N + tn0 + tx];
        float w1 = W[(size_t)(2*p + 1)*N + tn0 + tx];
        unsigned h, l; split2(w0, w1, h, l);
        th[ty4 + q][tx] = h;
        tl[ty4 + q][tx] = l;
    }
    __syncthreads();
    #pragma unroll
    for (int q = 0; q < 4; q++) {
        int n = tn0 + ty4 + q;
        Wh[(size_t)n*KP + tp0 + tx] = th[tx][ty4 + q];
        Wl[(size_t)n*KP + tp0 + tx] = tl[tx][ty4 + q];
    }
}

// ---------------- pairwise distances (pre-split fp16 3-term mma) ----------------
template<int F>
__global__ void __launch_bounds__(256, 2) distmma_k(
        const unsigned* __restrict__ Xh, const unsigned* __restrict__ Xl,
        int strideP, int offP) {
    constexpr int PAIRS = ((F + 15)/16)*8;
    constexpr int STR   = PAIRS + 4;
    __shared__ unsigned Ah[128*STR], Al[128*STR];
    __shared__ unsigned Bh[64*STR],  Bl[64*STR];
    int g  = blockIdx.z;
    int bm = blockIdx.y*128, bn = blockIdx.x*64;
    int tid = threadIdx.x, lane = tid & 31, warp = tid >> 5;
    int wm = warp & 3, wn = warp >> 2;
    int gid = lane >> 2, tig = lane & 3;
    int base = g*PTS;

    for (int e = tid; e < 32*PAIRS; e += 256) {
        int r = e / (PAIRS/4), c4 = (e % (PAIRS/4))*4;
        size_t go = (size_t)(base + bm + r)*strideP + offP + c4;
        *(uint4*)&Ah[r*STR + c4] = *(const uint4*)&Xh[go];
        *(uint4*)&Al[r*STR + c4] = *(const uint4*)&Xl[go];
    }
    for (int e = tid; e < 16*PAIRS; e += 256) {
        int r = e / (PAIRS/4), c4 = (e % (PAIRS/4))*4;
        size_t go = (size_t)(base + bn + r)*strideP + offP + c4;
        *(uint4*)&Bh[r*STR + c4] = *(const uint4*)&Xh[go];
        *(uint4*)&Bl[r*STR + c4] = *(const uint4*)&Xl[go];
    }
    __syncthreads();

    float acc[2][4][4] = {};
    #pragma unroll
    for (int s = 0; s < PAIRS/8; s++) {
        int p = s*8 + tig;
        unsigned ah[2][4], al[2][4];
        #pragma unroll
        for (int mi = 0; mi < 2; mi++) {
            int r = wm*32 + mi*16 + gid;
            ah[mi][0] = Ah[r*STR + p];       ah[mi][1] = Ah[(r+8)*STR + p];
            ah[mi][2] = Ah[r*STR + p + 4];   ah[mi][3] = Ah[(r+8)*STR + p + 4];
            al[mi][0] = Al[r*STR + p];       al[mi][1] = Al[(r+8)*STR + p];
            al[mi][2] = Al[r*STR + p + 4];   al[mi][3] = Al[(r+8)*STR + p + 4];
        }
        #pragma unroll
        for (int ni = 0; ni < 4; ni++) {
            int c = wn*32 + ni*8 + gid;
            unsigned bh0 = Bh[c*STR + p], bh1 = Bh[c*STR + p + 4];
            unsigned bl0 = Bl[c*STR + p], bl1 = Bl[c*STR + p + 4];
            #pragma unroll
            for (int mi = 0; mi < 2; mi++) {
                MMA_F16(acc[mi][ni], ah[mi][0],ah[mi][1],ah[mi][2],ah[mi][3], bh0,bh1);
                MMA_F16(acc[mi][ni], ah[mi][0],ah[mi][1],ah[mi][2],ah[mi][3], bl0,bl1);
                MMA_F16(acc[mi][ni], al[mi][0],al[mi][1],al[mi][2],al[mi][3], bh0,bh1);
            }
        }
    }
    #pragma unroll
    for (int mi = 0; mi < 2; mi++) {
        int row = bm + wm*32 + mi*16 + gid;
        float si0 = g_s[base + row];
        float si1 = g_s[base + row + 8];
        #pragma unroll
        for (int ni = 0; ni < 4; ni++) {
            int col = bn + wn*32 + ni*8 + 2*tig;
            float sj0 = g_s[base + col];
            float sj1 = g_s[base + col + 1];
            float2 o0 = make_float2(si0 + sj0 - 2.f*acc[mi][ni][0],
                                    si0 + sj1 - 2.f*acc[mi][ni][1]);
            float2 o1 = make_float2(si1 + sj0 - 2.f*acc[mi][ni][2],
                                    si1 + sj1 - 2.f*acc[mi][ni][3]);
            *(float2*)&g_big[(size_t)(base + row)*PTS + col]     = o0;
            *(float2*)&g_big[(size_t)(base + row + 8)*PTS + col] = o1;
        }
    }
}

// ---------------- top-K selection (REDUX min + top-3 cache; exact) ----------------
__global__ void topk_k() {
    int w = threadIdx.x >> 5, lane = threadIdx.x & 31;
    int i = blockIdx.x*8 + w;
    int g = i >> 10;
    const float* row = &g_big[(size_t)i*PTS];
    unsigned dl[32];
    #pragma unroll
    for (int t = 0; t < 32; t++) {
        int b = __float_as_int(row[lane + 32*t]);
        dl[t] = (unsigned)b ^ (0x80000000u | (unsigned)(b >> 31));  // monotone map
    }
    unsigned m1 = 0xFFFFFFFFu, m2 = 0xFFFFFFFFu, m3 = 0xFFFFFFFFu;
    int t1 = 0, t2 = 0, t3 = 0;
    #pragma unroll
    for (int t = 0; t < 32; t++) {
        unsigned v = dl[t];
        if (v < m1)      { m3 = m2; t3 = t2; m2 = m1; t2 = t1; m1 = v; t1 = t; }
        else if (v < m2) { m3 = m2; t3 = t2; m2 = v; t2 = t; }
        else if (v < m3) { m3 = v; t3 = t; }
    }
    int avail = 3;
    for (int kk = 0; kk < KNB; kk++) {
        unsigned umin = __reduce_min_sync(0xffffffffu, m1);
        unsigned myjv = (m1 == umin) ? (unsigned)(lane + 32*t1) : 0xFFFFFFFFu;
        unsigned jv = __reduce_min_sync(0xffffffffu, myjv);
        if (lane == 0) g_idx[(size_t)i*KNB + kk] = (g << 10) + (int)jv;
        if ((jv & 31) == lane) {
            int rt = (int)(jv >> 5);
            #pragma unroll
            for (int t = 0; t < 32; t++) if (t == rt) dl[t] = 0xFFFFFFFFu;
            if (--avail > 0) {
                m1 = m2; t1 = t2; m2 = m3; t2 = t3; m3 = 0xFFFFFFFFu;
            } else {
                m1 = 0xFFFFFFFFu; m2 = 0xFFFFFFFFu; m3 = 0xFFFFFFFFu;
                t1 = 0; t2 = 0; t3 = 0;
                #pragma unroll
                for (int t = 0; t < 32; t++) {
                    unsigned vv = dl[t];
                    if (vv < m1)      { m3 = m2; t3 = t2; m2 = m1; t2 = t1; m1 = vv; t1 = t; }
                    else if (vv < m2) { m3 = m2; t3 = t2; m2 = vv; t2 = t; }
                    else if (vv < m3) { m3 = vv; t3 = t; }
                }
                avail = 3;
            }
        }
    }
}

// ---------------- precompute B/C (+ squared norms fused) ----------------
template<int F>
__global__ void precompute_k(const float* __restrict__ x, int ldx,
                             const float* __restrict__ W1, const float* __restrict__ b1) {
    int gid = blockIdx.x*256 + threadIdx.x;
    int i = gid >> 6, c = gid & 63;
    const float* xr = x + (size_t)i*ldx;
    float a = 0.f, b = 0.f, s = 0.f;
    #pragma unroll
    for (int f = 0; f < F; f++) {
        float xv = xr[f];
        a += xv * W1[f*DIM + c];
        b += xv * W1[(F + f)*DIM + c];
        s += xv * xv;
    }
    g_B[gid] = b;
    g_C[gid] = a - b + b1[c];
    if (c == 0) g_s[i] = s;
}

// ---------------- edgeconv W2 prep ----------------
__global__ void w2prep_k(const float* __restrict__ W2) {
    int e = blockIdx.x*256 + threadIdx.x;
    int n = e & 63, j = e >> 6;
    float w0 = W2[(2*j)*64 + n];
    float w1 = W2[(2*j+1)*64 + n];
    unsigned h, l; split2(w0, w1, h, l);
    g_w2h[n*32 + j] = h;
    g_w2l[n*32 + j] = l;
}

// ---------------- edgeconv ----------------
template<bool AL, bool SPLITLO>
__global__ void __launch_bounds__(128) edgeconv_k(
        const float* __restrict__ b2, float* __restrict__ out, int ldo,
        unsigned* __restrict__ oh, unsigned* __restrict__ ol) {
    __shared__ unsigned Hh[4][32][36];
    __shared__ unsigned Hl[4][32][36];
    int tid = threadIdx.x, lane = tid & 31, warp = tid >> 5;
    int gid = lane >> 2, tig = lane & 3;
    int i = blockIdx.x*4 + warp;

    unsigned (*hh)[36] = Hh[warp];
    unsigned (*hl)[36] = Hl[warp];
    const int* idxr = g_idx + (size_t)i*KNB;
    float2 cv = *(const float2*)&g_C[(size_t)i*DIM + 2*lane];
    #pragma unroll
    for (int k = 0; k < 32; k++) {
        int j = idxr[(k < KNB) ? k : 0];
        float2 bv = *(const float2*)&g_B[(size_t)j*DIM + 2*lane];
        float f0 = fmaxf(cv.x + bv.x, 0.f);
        float f1 = fmaxf(cv.y + bv.y, 0.f);
        unsigned h, l; split2(f0, f1, h, l);
        hh[k][lane] = h;
        if (AL) hl[k][lane] = l;
    }
    __syncwarp();

    float acc[2][8][4] = {};
    #pragma unroll
    for (int s = 0; s < 4; s++) {
        int p = s*8 + tig;
        unsigned ah[2][4], al[2][4];
        #pragma unroll
        for (int mi = 0; mi < 2; mi++) {
            int r = mi*16 + gid;
            ah[mi][0] = hh[r][p];   ah[mi][1] = hh[r+8][p];
            ah[mi][2] = hh[r][p+4]; ah[mi][3] = hh[r+8][p+4];
            if (AL) {
                al[mi][0] = hl[r][p];   al[mi][1] = hl[r+8][p];
                al[mi][2] = hl[r][p+4]; al[mi][3] = hl[r+8][p+4];
            }
        }
        #pragma unroll
        for (int ni = 0; ni < 8; ni++) {
            int c = ni*8 + gid;
            unsigned bh0 = g_w2h[c*32 + p], bh1 = g_w2h[c*32 + p + 4];
            unsigned bl0 = g_w2l[c*32 + p], bl1 = g_w2l[c*32 + p + 4];
            #pragma unroll
            for (int mi = 0; mi < 2; mi++) {
                MMA_F16(acc[mi][ni], ah[mi][0],ah[mi][1],ah[mi][2],ah[mi][3], bh0,bh1);
                MMA_F16(acc[mi][ni], ah[mi][0],ah[mi][1],ah[mi][2],ah[mi][3], bl0,bl1);
                if (AL)
                    MMA_F16(acc[mi][ni], al[mi][0],al[mi][1],al[mi][2],al[mi][3], bh0,bh1);
            }
        }
    }
    #pragma unroll
    for (int ni = 0; ni < 8; ni++) {
        float m0 = fmaxf(fmaxf(acc[0][ni][0], acc[0][ni][2]),
                         fmaxf(acc[1][ni][0], acc[1][ni][2]));
        float m1 = fmaxf(fmaxf(acc[0][ni][1], acc[0][ni][3]),
                         fmaxf(acc[1][ni][1], acc[1][ni][3]));
        m0 = fmaxf(m0, __shfl_xor_sync(0xffffffffu, m0, 4));
        m1 = fmaxf(m1, __shfl_xor_sync(0xffffffffu, m1, 4));
        m0 = fmaxf(m0, __shfl_xor_sync(0xffffffffu, m0, 8));
        m1 = fmaxf(m1, __shfl_xor_sync(0xffffffffu, m1, 8));
        m0 = fmaxf(m0, __shfl_xor_sync(0xffffffffu, m0, 16));
        m1 = fmaxf(m1, __shfl_xor_sync(0xffffffffu, m1, 16));
        if (gid == 0) {
            int col = ni*8 + tig*2;
            float2 bz = *(const float2*)&b2[col];
            float o0 = fmaxf(m0 + bz.x, 0.f);
            float o1 = fmaxf(m1 + bz.y, 0.f);
            *(float2*)&out[(size_t)i*ldo + col] = make_float2(o0, o1);
            unsigned h, l; split2(o0, o1, h, l);
            oh[(size_t)i*96 + (col >> 1)] = h;
            if (SPLITLO) ol[(size_t)i*96 + (col >> 1)] = l;
        }
    }
}

// ---------------- wide-M pre-split GEMM with internal N loop ----------------
template<bool SPLITLO, int NT>
__global__ void __launch_bounds__(256, 2) hgemm_w(
        const unsigned* __restrict__ Ah_g,
        const unsigned* __restrict__ Wh_g, const unsigned* __restrict__ Wl_g,
        const float* __restrict__ bias,
        unsigned* __restrict__ Oh, unsigned* __restrict__ Ol,
        int KP, int Nd) {
    __shared__ unsigned Ahs[256*20];
    __shared__ unsigned Bhs[64*20], Bls[64*20];
    int tid  = threadIdx.x;
    int lane = tid & 31, warp = tid >> 5;
    int wm = warp & 3, wn = warp >> 2;
    int gid = lane >> 2, tig = lane & 3;
    int bm = blockIdx.y * 256;
    int NdP = Nd >> 1;

    #pragma unroll 1
    for (int nt = 0; nt < NT; nt++) {
        int bn = (blockIdx.x*NT + nt)*64;
        float acc[4][4][4] = {};
        #pragma unroll 1
        for (int k0p = 0; k0p < KP; k0p += 16) {
            uint4 ra[4], rbh, rbl;
            #pragma unroll
            for (int q = 0; q < 4; q++) {
                int e = q*256 + tid;
                int r = e >> 2, c4 = (e & 3)*4;
                ra[q] = *(const uint4*)&Ah_g[(size_t)(bm + r)*KP + k0p + c4];
            }
            {
                int r = tid >> 2, c4 = (tid & 3)*4;
                size_t go = (size_t)(bn + r)*KP + k0p + c4;
                rbh = *(const uint4*)&Wh_g[go];
                rbl = *(const uint4*)&Wl_g[go];
            }
            __syncthreads();
            #pragma unroll
            for (int q = 0; q < 4; q++) {
                int e = q*256 + tid;
                int r = e >> 2, c4 = (e & 3)*4;
                *(uint4*)&Ahs[r*20 + c4] = ra[q];
            }
            {
                int r = tid >> 2, c4 = (tid & 3)*4;
                *(uint4*)&Bhs[r*20 + c4] = rbh;
                *(uint4*)&Bls[r*20 + c4] = rbl;
            }
            __syncthreads();
            #pragma unroll
            for (int s = 0; s < 2; s++) {
                int p = s*8 + tig;
                unsigned ah[4][4];
                #pragma unroll
                for (int mi = 0; mi < 4; mi++) {
                    int r = wm*64 + mi*16 + gid;
                    ah[mi][0] = Ahs[r*20 + p];       ah[mi][1] = Ahs[(r+8)*20 + p];
                    ah[mi][2] = Ahs[r*20 + p + 4];   ah[mi][3] = Ahs[(r+8)*20 + p + 4];
                }
                #pragma unroll
                for (int ni = 0; ni < 4; ni++) {
                    int c = wn*32 + ni*8 + gid;
                    unsigned bh0 = Bhs[c*20 + p], bh1 = Bhs[c*20 + p + 4];
                    unsigned bl0 = Bls[c*20 + p], bl1 = Bls[c*20 + p + 4];
                    #pragma unroll
                    for (int mi = 0; mi < 4; mi++) {
                        MMA_F16(acc[mi][ni], ah[mi][0],ah[mi][1],ah[mi][2],ah[mi][3], bh0,bh1);
                        MMA_F16(acc[mi][ni], ah[mi][0],ah[mi][1],ah[mi][2],ah[mi][3], bl0,bl1);
                    }
                }
            }
        }
        #pragma unroll
        for (int mi = 0; mi < 4; mi++) {
            int row = bm + wm*64 + mi*16 + gid;
            #pragma unroll
            for (int ni = 0; ni < 4; ni++) {
                int col = bn + wn*32 + ni*8 + tig*2;
                float bz0 = bias[col], bz1 = bias[col+1];
                float z0 = fmaxf(acc[mi][ni][0] + bz0, 0.f);
                float z1 = fmaxf(acc[mi][ni][1] + bz1, 0.f);
                float z2 = fmaxf(acc[mi][ni][2] + bz0, 0.f);
                float z3 = fmaxf(acc[mi][ni][3] + bz1, 0.f);
                unsigned h, l;
                split2(z0, z1, h, l);
                Oh[(size_t)row*NdP + (col >> 1)] = h;
                if (SPLITLO) Ol[(size_t)row*NdP + (col >> 1)] = l;
                split2(z2, z3, h, l);
                Oh[(size_t)(row+8)*NdP + (col >> 1)] = h;
                if (SPLITLO) Ol[(size_t)(row+8)*NdP + (col >> 1)] = l;
            }
        }
    }
}

// ---------------- pre-split fp16 GEMM (3-term, small layers) ----------------
template<bool RELU, bool SPLITOUT>
__global__ void __launch_bounds__(256, 2) hgemm_ps(
        const unsigned* __restrict__ Ah_g, const unsigned* __restrict__ Al_g,
        const unsigned* __restrict__ Wh_g, const unsigned* __restrict__ Wl_g,
        const float* __restrict__ bias,
        unsigned* __restrict__ Oh, unsigned* __restrict__ Ol,
        float* __restrict__ Of, int KP, int Nd) {
    __shared__ unsigned Ahs[128*20], Als[128*20];
    __shared__ unsigned Bhs[64*20],  Bls[64*20];
    int tid  = threadIdx.x;
    int lane = tid & 31, warp = tid >> 5;
    int wm = warp & 3, wn = warp >> 2;
    int gid = lane >> 2, tig = lane & 3;
    int bm = blockIdx.y * 128, bn = blockIdx.x * 64;
    float acc[2][4][4] = {};

    for (int k0p = 0; k0p < KP; k0p += 16) {
        uint4 rah[2], ral[2], rbh, rbl;
        #pragma unroll
        for (int q = 0; q < 2; q++) {
            int e = q*256 + tid;
            int r = e >> 2, c4 = (e & 3)*4;
            size_t go = (size_t)(bm + r)*KP + k0p + c4;
            rah[q] = *(const uint4*)&Ah_g[go];
            ral[q] = *(const uint4*)&Al_g[go];
        }
        {
            int r = tid >> 2, c4 = (tid & 3)*4;
            size_t go = (size_t)(bn + r)*KP + k0p + c4;
            rbh = *(const uint4*)&Wh_g[go];
            rbl = *(const uint4*)&Wl_g[go];
        }
        __syncthreads();
        #pragma unroll
        for (int q = 0; q < 2; q++) {
            int e = q*256 + tid;
            int r = e >> 2, c4 = (e & 3)*4;
            *(uint4*)&Ahs[r*20 + c4] = rah[q];
            *(uint4*)&Als[r*20 + c4] = ral[q];
        }
        {
            int r = tid >> 2, c4 = (tid & 3)*4;
            *(uint4*)&Bhs[r*20 + c4] = rbh;
            *(uint4*)&Bls[r*20 + c4] = rbl;
        }
        __syncthreads();
        #pragma unroll
        for (int s = 0; s < 2; s++) {
            int p = s*8 + tig;
            unsigned ah[2][4], al[2][4];
            #pragma unroll
            for (int mi = 0; mi < 2; mi++) {
                int r = wm*32 + mi*16 + gid;
                ah[mi][0] = Ahs[r*20 + p];       ah[mi][1] = Ahs[(r+8)*20 + p];
                ah[mi][2] = Ahs[r*20 + p + 4];   ah[mi][3] = Ahs[(r+8)*20 + p + 4];
                al[mi][0] = Als[r*20 + p];       al[mi][1] = Als[(r+8)*20 + p];
                al[mi][2] = Als[r*20 + p + 4];   al[mi][3] = Als[(r+8)*20 + p + 4];
            }
            #pragma unroll
            for (int ni = 0; ni < 4; ni++) {
                int c = wn*32 + ni*8 + gid;
                unsigned bh0 = Bhs[c*20 + p], bh1 = Bhs[c*20 + p + 4];
                unsigned bl0 = Bls[c*20 + p], bl1 = Bls[c*20 + p + 4];
                #pragma unroll
                for (int mi = 0; mi < 2; mi++) {
                    MMA_F16(acc[mi][ni], ah[mi][0],ah[mi][1],ah[mi][2],ah[mi][3], bh0,bh1);
                    MMA_F16(acc[mi][ni], ah[mi][0],ah[mi][1],ah[mi][2],ah[mi][3], bl0,bl1);
                    MMA_F16(acc[mi][ni], al[mi][0],al[mi][1],al[mi][2],al[mi][3], bh0,bh1);
                }
            }
        }
    }
    int NdP = Nd >> 1;
    #pragma unroll
    for (int mi = 0; mi < 2; mi++) {
        int row = bm + wm*32 + mi*16 + gid;
        #pragma unroll
        for (int ni = 0; ni < 4; ni++) {
            int col = bn + wn*32 + ni*8 + tig*2;
            float bz0 = bias[col], bz1 = bias[col+1];
            float z0 = acc[mi][ni][0] + bz0;
            float z1 = acc[mi][ni][1] + bz1;
            float z2 = acc[mi][ni][2] + bz0;
            float z3 = acc[mi][ni][3] + bz1;
            if (RELU) {
                z0 = fmaxf(z0, 0.f); z1 = fmaxf(z1, 0.f);
                z2 = fmaxf(z2, 0.f); z3 = fmaxf(z3, 0.f);
            }
            if (SPLITOUT) {
                unsigned h, l;
                split2(z0, z1, h, l);
                Oh[(size_t)row*NdP + (col >> 1)] = h;
                Ol[(size_t)row*NdP + (col >> 1)] = l;
                split2(z2, z3, h, l);
                Oh[(size_t)(row+8)*NdP + (col >> 1)] = h;
                Ol[(size_t)(row+8)*NdP + (col >> 1)] = l;
            } else {
                *(float2*)&Of[(size_t)row*Nd + col]     = make_float2(z0, z1);
                *(float2*)&Of[(size_t)(row+8)*Nd + col] = make_float2(z2, z3);
            }
        }
    }
}

// ---------------- host orchestration ----------------
template<int F, bool EAL>
static void run_conv(const float* xp, int ldx,
                     const unsigned* xh, const unsigned* xl, int strideP, int offP,
                     const float* w1, const float* b1,
                     const float* w2, const float* b2,
                     float* outp, unsigned* oh, unsigned* ol) {
    precompute_k<F><<<(NPT*DIM)/256, 256>>>(xp, ldx, w1, b1);
    distmma_k<F><<<dim3(PTS/64, PTS/128, NG), 256>>>(xh, xl, strideP, offP);
    topk_k<<<NPT/8, 256>>>();
    w2prep_k<<<8, 256>>>(w2);
    edgeconv_k<EAL, EAL><<<NPT/4, 128>>>(b2, outp, 192, oh, ol);
}

extern "C" void kernel_launch(void* const* d_in, const int* in_sizes, int n_in,
                              void* d_out, int out_size) {
    const float* x    = (const float*)d_in[0];
    const float* c1w1 = (const float*)d_in[2];
    const float* c1b1 = (const float*)d_in[3];
    const float* c1w2 = (const float*)d_in[4];
    const float* c1b2 = (const float*)d_in[5];
    const float* c2w1 = (const float*)d_in[6];
    const float* c2b1 = (const float*)d_in[7];
    const float* c2w2 = (const float*)d_in[8];
    const float* c2b2 = (const float*)d_in[9];
    const float* c3w1 = (const float*)d_in[10];
    const float* c3b1 = (const float*)d_in[11];
    const float* c3w2 = (const float*)d_in[12];
    const float* c3b2 = (const float*)d_in[13];
    const float* lw   = (const float*)d_in[14];
    const float* lb   = (const float*)d_in[15];
    const float* hw1  = (const float*)d_in[16];
    const float* hb1  = (const float*)d_in[17];
    const float* hw2  = (const float*)d_in[18];
    const float* hb2  = (const float*)d_in[19];
    const float* hw3  = (const float*)d_in[20];
    const float* hb3  = (const float*)d_in[21];
    float* out = (float*)d_out;

    float *hcat, *big, *h1b, *h2b;
    unsigned *x1h, *x1l, *ah0, *al0;
    unsigned *wlh, *wll, *w1h, *w1l, *w2h, *w2l, *w3h, *w3l;
    cudaGetSymbolAddress((void**)&hcat, g_hcat);
    cudaGetSymbolAddress((void**)&big,  g_big);
    cudaGetSymbolAddress((void**)&h1b,  g_h1);
    cudaGetSymbolAddress((void**)&h2b,  g_h2);
    cudaGetSymbolAddress((void**)&x1h,  g_x1h);
    cudaGetSymbolAddress((void**)&x1l,  g_x1l);
    cudaGetSymbolAddress((void**)&ah0,  g_ah0);
    cudaGetSymbolAddress((void**)&al0,  g_al0);
    cudaGetSymbolAddress((void**)&wlh,  g_wlh);
    cudaGetSymbolAddress((void**)&wll,  g_wll);
    cudaGetSymbolAddress((void**)&w1h,  g_hw1h);
    cudaGetSymbolAddress((void**)&w1l,  g_hw1l);
    cudaGetSymbolAddress((void**)&w2h,  g_hw2h);
    cudaGetSymbolAddress((void**)&w2l,  g_hw2l);
    cudaGetSymbolAddress((void**)&w3h,  g_hw3h);
    cudaGetSymbolAddress((void**)&w3l,  g_hw3l);

    unsigned* a1h = (unsigned*)big;  unsigned* a1l = a1h + (size_t)NPT*512;
    unsigned* a2h = (unsigned*)h1b;  unsigned* a2l = a2h + (size_t)NPT*128;
    unsigned* a3h = (unsigned*)h2b;  unsigned* a3l = a3h + (size_t)NPT*64;

    splitx1_k<<<(NPT*8)/256, 256>>>(x);

    run_conv<14, true >(x,         14,  x1h, x1l, 8,  0,  c1w1, c1b1, c1w2, c1b2,
                        hcat,       ah0,      al0);
    run_conv<64, true >(hcat,      192, ah0, al0, 96, 0,  c2w1, c2b1, c2w2, c2b2,
                        hcat + 64,  ah0 + 32, al0 + 32);
    run_conv<64, false>(hcat + 64, 192, ah0, al0, 96, 32, c3w1, c3b1, c3w2, c3b2,
                        hcat + 128, ah0 + 64, al0 + 64);

    // coalesced weight prep (32x32 smem transpose tiles)
    wprep_k<<<dim3(96/32,  1024/32), 256>>>(lw,  wlh, wll, 192,  1024);
    wprep_k<<<dim3(512/32, 256/32),  256>>>(hw1, w1h, w1l, 1024, 256);
    wprep_k<<<dim3(128/32, 128/32),  256>>>(hw2, w2h, w2l, 256,  128);
    wprep_k<<<dim3(64/32,  64/32),   256>>>(hw3, w3h, w3l, 128,  64);

    hgemm_w<false, 4><<<dim3(4, 128), 256>>>(ah0, wlh, wll, lb,  a1h, nullptr, 96,  1024);
    hgemm_w<true,  2><<<dim3(2, 128), 256>>>(a1h, w1h, w1l, hb1, a2h, a2l,     512, 256);
    hgemm_ps<true,  true ><<<dim3(2, 256), 256>>>(a2h, a2l, w2h, w2l, hb2, a3h, a3l, nullptr, 128, 128);
    hgemm_ps<false, false><<<dim3(1, 256), 256>>>(a3h, a3l, w3h, w3l, hb3, nullptr, nullptr, out, 64, 64);
}

// round 15
// speedup vs baseline: 1.1179x; 1.0161x over previous
#include <cuda_runtime.h>
#include <cuda_fp16.h>
#include <cstdint>
#include <cstddef>
#include <math.h>
#include <float.h>

#define NG   32
#define PTS  1024
#define NPT  (NG*PTS)      // 32768
#define KNB  30
#define DIM  64

// ---------------- device scratch (static, no allocations) ----------------
__device__ float g_s[NPT];
__device__ int   g_idx[NPT*KNB];
__device__ float g_B[NPT*DIM];
__device__ float g_C[NPT*DIM];
__device__ float g_hcat[NPT*192];
__device__ float g_big[(size_t)NPT*1024];   // dist matrix; later a1h/a1l split buffers
__device__ float g_h1[NPT*256];             // later a2h/a2l
__device__ float g_h2[NPT*128];             // later a3h/a3l
__device__ unsigned g_w2h[64*32];
__device__ unsigned g_w2l[64*32];
__device__ unsigned g_x1h[NPT*8],  g_x1l[NPT*8];
__device__ unsigned g_ah0[NPT*96], g_al0[NPT*96];
__device__ unsigned g_wlh[1024*96],  g_wll[1024*96];
__device__ unsigned g_hw1h[256*512], g_hw1l[256*512];
__device__ unsigned g_hw2h[128*128], g_hw2l[128*128];
__device__ unsigned g_hw3h[64*64],   g_hw3l[64*64];

// ---------------- fp16 split helpers ----------------
__device__ __forceinline__ void split2(float x, float y, unsigned& h, unsigned& l) {
    __half2 p = __floats2half2_rn(x, y);
    h = *reinterpret_cast<unsigned*>(&p);
    float rx = x - __low2float(p);
    float ry = y - __high2float(p);
    __half2 q = __floats2half2_rn(rx, ry);
    l = *reinterpret_cast<unsigned*>(&q);
}

#define MMA_F16(d, a0,a1,a2,a3, b0,b1) \
    asm volatile("mma.sync.aligned.m16n8k16.row.col.f32.f16.f16.f32 " \
        "{%0,%1,%2,%3}, {%4,%5,%6,%7}, {%8,%9}, {%0,%1,%2,%3};" \
        : "+f"(d[0]),"+f"(d[1]),"+f"(d[2]),"+f"(d[3]) \
        : "r"(a0),"r"(a1),"r"(a2),"r"(a3), "r"(b0),"r"(b1))

// ---------------- prep kernels ----------------
__global__ void splitx1_k(const float* __restrict__ x) {
    int e = blockIdx.x*256 + threadIdx.x;
    int i = e >> 3, p = e & 7;
    float v0 = 0.f, v1 = 0.f;
    if (p < 7) { v0 = x[i*14 + 2*p]; v1 = x[i*14 + 2*p + 1]; }
    unsigned h, l; split2(v0, v1, h, l);
    g_x1h[e] = h; g_x1l[e] = l;
}

// coalesced transpose-split: W [K][N] fp32 -> Wh/Wl [N][KP] fp16-pair words.
__global__ void wprep_k(const float* __restrict__ W, unsigned* __restrict__ Wh,
                        unsigned* __restrict__ Wl, int K, int N) {
    __shared__ unsigned th[32][33], tl[32][33];
    int KP = K >> 1;
    int tp0 = blockIdx.x*32, tn0 = blockIdx.y*32;
    int tx = threadIdx.x & 31, ty4 = (threadIdx.x >> 5)*4;
    #pragma unroll
    for (int q = 0; q < 4; q++) {
        int p = tp0 + ty4 + q;
        float w0 = W[(size_t)(2*p)*N + tn0 + tx];
        float w1 = W[(size_t)(2*p + 1)*N + tn0 + tx];
        unsigned h, l; split2(w0, w1, h, l);
        th[ty4 + q][tx] = h;
        tl[ty4 + q][tx] = l;
    }
    __syncthreads();
    #pragma unroll
    for (int q = 0; q < 4; q++) {
        int n = tn0 + ty4 + q;
        Wh[(size_t)n*KP + tp0 + tx] = th[tx][ty4 + q];
        Wl[(size_t)n*KP + tp0 + tx] = tl[tx][ty4 + q];
    }
}

// ---------------- pairwise distances (pre-split fp16 3-term mma) ----------------
template<int F>
__global__ void __launch_bounds__(256, 2) distmma_k(
        const unsigned* __restrict__ Xh, const unsigned* __restrict__ Xl,
        int strideP, int offP) {
    constexpr int PAIRS = ((F + 15)/16)*8;
    constexpr int STR   = PAIRS + 4;
    __shared__ unsigned Ah[128*STR], Al[128*STR];
    __shared__ unsigned Bh[64*STR],  Bl[64*STR];
    int g  = blockIdx.z;
    int bm = blockIdx.y*128, bn = blockIdx.x*64;
    int tid = threadIdx.x, lane = tid & 31, warp = tid >> 5;
    int wm = warp & 3, wn = warp >> 2;
    int gid = lane >> 2, tig = lane & 3;
    int base = g*PTS;

    for (int e = tid; e < 32*PAIRS; e += 256) {
        int r = e / (PAIRS/4), c4 = (e % (PAIRS/4))*4;
        size_t go = (size_t)(base + bm + r)*strideP + offP + c4;
        *(uint4*)&Ah[r*STR + c4] = *(const uint4*)&Xh[go];
        *(uint4*)&Al[r*STR + c4] = *(const uint4*)&Xl[go];
    }
    for (int e = tid; e < 16*PAIRS; e += 256) {
        int r = e / (PAIRS/4), c4 = (e % (PAIRS/4))*4;
        size_t go = (size_t)(base + bn + r)*strideP + offP + c4;
        *(uint4*)&Bh[r*STR + c4] = *(const uint4*)&Xh[go];
        *(uint4*)&Bl[r*STR + c4] = *(const uint4*)&Xl[go];
    }
    __syncthreads();

    float acc[2][4][4] = {};
    #pragma unroll
    for (int s = 0; s < PAIRS/8; s++) {
        int p = s*8 + tig;
        unsigned ah[2][4], al[2][4];
        #pragma unroll
        for (int mi = 0; mi < 2; mi++) {
            int r = wm*32 + mi*16 + gid;
            ah[mi][0] = Ah[r*STR + p];       ah[mi][1] = Ah[(r+8)*STR + p];
            ah[mi][2] = Ah[r*STR + p + 4];   ah[mi][3] = Ah[(r+8)*STR + p + 4];
            al[mi][0] = Al[r*STR + p];       al[mi][1] = Al[(r+8)*STR + p];
            al[mi][2] = Al[r*STR + p + 4];   al[mi][3] = Al[(r+8)*STR + p + 4];
        }
        #pragma unroll
        for (int ni = 0; ni < 4; ni++) {
            int c = wn*32 + ni*8 + gid;
            unsigned bh0 = Bh[c*STR + p], bh1 = Bh[c*STR + p + 4];
            unsigned bl0 = Bl[c*STR + p], bl1 = Bl[c*STR + p + 4];
            #pragma unroll
            for (int mi = 0; mi < 2; mi++) {
                MMA_F16(acc[mi][ni], ah[mi][0],ah[mi][1],ah[mi][2],ah[mi][3], bh0,bh1);
                MMA_F16(acc[mi][ni], ah[mi][0],ah[mi][1],ah[mi][2],ah[mi][3], bl0,bl1);
                MMA_F16(acc[mi][ni], al[mi][0],al[mi][1],al[mi][2],al[mi][3], bh0,bh1);
            }
        }
    }
    #pragma unroll
    for (int mi = 0; mi < 2; mi++) {
        int row = bm + wm*32 + mi*16 + gid;
        float si0 = g_s[base + row];
        float si1 = g_s[base + row + 8];
        #pragma unroll
        for (int ni = 0; ni < 4; ni++) {
            int col = bn + wn*32 + ni*8 + 2*tig;
            float sj0 = g_s[base + col];
            float sj1 = g_s[base + col + 1];
            float2 o0 = make_float2(si0 + sj0 - 2.f*acc[mi][ni][0],
                                    si0 + sj1 - 2.f*acc[mi][ni][1]);
            float2 o1 = make_float2(si1 + sj0 - 2.f*acc[mi][ni][2],
                                    si1 + sj1 - 2.f*acc[mi][ni][3]);
            *(float2*)&g_big[(size_t)(base + row)*PTS + col]     = o0;
            *(float2*)&g_big[(size_t)(base + row + 8)*PTS + col] = o1;
        }
    }
}

// ---------------- top-K selection (64-bit key cache, no invalidation; exact) ----
// key = (monotone_u32(d) << 6) | (slot+1): strictly ordered by (d, slot), unique.
// Each lane keeps lastk = largest consumed key and a sorted cache k1<=k2<=k3 of
// the next candidates > lastk. Consumption pops the cache; rescan only on drain.
__global__ void topk_k() {
    int w = threadIdx.x >> 5, lane = threadIdx.x & 31;
    int i = blockIdx.x*8 + w;
    int g = i >> 10;
    const float* row = &g_big[(size_t)i*PTS];
    unsigned dl[32];
    #pragma unroll
    for (int t = 0; t < 32; t++) {
        int b = __float_as_int(row[lane + 32*t]);
        dl[t] = (unsigned)b ^ (0x80000000u | (unsigned)(b >> 31));  // monotone map
    }
    unsigned long long lastk = 0ull;
    unsigned long long k1 = ~0ull, k2 = ~0ull, k3 = ~0ull;
    #pragma unroll
    for (int t = 0; t < 32; t++) {
        unsigned long long key = ((unsigned long long)dl[t] << 6) | (unsigned)(t + 1);
        if (key < k1)      { k3 = k2; k2 = k1; k1 = key; }
        else if (key < k2) { k3 = k2; k2 = key; }
        else if (key < k3) { k3 = key; }
    }
    for (int kk = 0; kk < KNB; kk++) {
        unsigned m1 = (unsigned)(k1 >> 6);
        unsigned umin = __reduce_min_sync(0xffffffffu, m1);
        int t1 = (int)(k1 & 63) - 1;
        unsigned myjv = (m1 == umin) ? (unsigned)(lane + 32*t1) : 0xFFFFFFFFu;
        unsigned jv = __reduce_min_sync(0xffffffffu, myjv);
        if (lane == 0) g_idx[(size_t)i*KNB + kk] = (g << 10) + (int)jv;
        if ((jv & 31) == lane) {
            lastk = k1;
            k1 = k2; k2 = k3; k3 = ~0ull;
            if (k1 == ~0ull) {                 // cache drained: rescan > lastk
                k2 = ~0ull; k3 = ~0ull;
                #pragma unroll
                for (int t = 0; t < 32; t++) {
                    unsigned long long key =
                        ((unsigned long long)dl[t] << 6) | (unsigned)(t + 1);
                    if (key > lastk) {
                        if (key < k1)      { k3 = k2; k2 = k1; k1 = key; }
                        else if (key < k2) { k3 = k2; k2 = key; }
                        else if (key < k3) { k3 = key; }
                    }
                }
            }
        }
    }
}

// ---------------- precompute B/C (+ squared norms fused) ----------------
template<int F>
__global__ void precompute_k(const float* __restrict__ x, int ldx,
                             const float* __restrict__ W1, const float* __restrict__ b1) {
    int gid = blockIdx.x*256 + threadIdx.x;
    int i = gid >> 6, c = gid & 63;
    const float* xr = x + (size_t)i*ldx;
    float a = 0.f, b = 0.f, s = 0.f;
    #pragma unroll
    for (int f = 0; f < F; f++) {
        float xv = xr[f];
        a += xv * W1[f*DIM + c];
        b += xv * W1[(F + f)*DIM + c];
        s += xv * xv;
    }
    g_B[gid] = b;
    g_C[gid] = a - b + b1[c];
    if (c == 0) g_s[i] = s;
}

// ---------------- edgeconv W2 prep ----------------
__global__ void w2prep_k(const float* __restrict__ W2) {
    int e = blockIdx.x*256 + threadIdx.x;
    int n = e & 63, j = e >> 6;
    float w0 = W2[(2*j)*64 + n];
    float w1 = W2[(2*j+1)*64 + n];
    unsigned h, l; split2(w0, w1, h, l);
    g_w2h[n*32 + j] = h;
    g_w2l[n*32 + j] = l;
}

// ---------------- edgeconv ----------------
template<bool AL, bool SPLITLO>
__global__ void __launch_bounds__(128) edgeconv_k(
        const float* __restrict__ b2, float* __restrict__ out, int ldo,
        unsigned* __restrict__ oh, unsigned* __restrict__ ol) {
    __shared__ unsigned Hh[4][32][36];
    __shared__ unsigned Hl[4][32][36];
    int tid = threadIdx.x, lane = tid & 31, warp = tid >> 5;
    int gid = lane >> 2, tig = lane & 3;
    int i = blockIdx.x*4 + warp;

    unsigned (*hh)[36] = Hh[warp];
    unsigned (*hl)[36] = Hl[warp];
    const int* idxr = g_idx + (size_t)i*KNB;
    float2 cv = *(const float2*)&g_C[(size_t)i*DIM + 2*lane];
    #pragma unroll
    for (int k = 0; k < 32; k++) {
        int j = idxr[(k < KNB) ? k : 0];
        float2 bv = *(const float2*)&g_B[(size_t)j*DIM + 2*lane];
        float f0 = fmaxf(cv.x + bv.x, 0.f);
        float f1 = fmaxf(cv.y + bv.y, 0.f);
        unsigned h, l; split2(f0, f1, h, l);
        hh[k][lane] = h;
        if (AL) hl[k][lane] = l;
    }
    __syncwarp();

    float acc[2][8][4] = {};
    #pragma unroll
    for (int s = 0; s < 4; s++) {
        int p = s*8 + tig;
        unsigned ah[2][4], al[2][4];
        #pragma unroll
        for (int mi = 0; mi < 2; mi++) {
            int r = mi*16 + gid;
            ah[mi][0] = hh[r][p];   ah[mi][1] = hh[r+8][p];
            ah[mi][2] = hh[r][p+4]; ah[mi][3] = hh[r+8][p+4];
            if (AL) {
                al[mi][0] = hl[r][p];   al[mi][1] = hl[r+8][p];
                al[mi][2] = hl[r][p+4]; al[mi][3] = hl[r+8][p+4];
            }
        }
        #pragma unroll
        for (int ni = 0; ni < 8; ni++) {
            int c = ni*8 + gid;
            unsigned bh0 = g_w2h[c*32 + p], bh1 = g_w2h[c*32 + p + 4];
            unsigned bl0 = g_w2l[c*32 + p], bl1 = g_w2l[c*32 + p + 4];
            #pragma unroll
            for (int mi = 0; mi < 2; mi++) {
                MMA_F16(acc[mi][ni], ah[mi][0],ah[mi][1],ah[mi][2],ah[mi][3], bh0,bh1);
                MMA_F16(acc[mi][ni], ah[mi][0],ah[mi][1],ah[mi][2],ah[mi][3], bl0,bl1);
                if (AL)
                    MMA_F16(acc[mi][ni], al[mi][0],al[mi][1],al[mi][2],al[mi][3], bh0,bh1);
            }
        }
    }
    #pragma unroll
    for (int ni = 0; ni < 8; ni++) {
        float m0 = fmaxf(fmaxf(acc[0][ni][0], acc[0][ni][2]),
                         fmaxf(acc[1][ni][0], acc[1][ni][2]));
        float m1 = fmaxf(fmaxf(acc[0][ni][1], acc[0][ni][3]),
                         fmaxf(acc[1][ni][1], acc[1][ni][3]));
        m0 = fmaxf(m0, __shfl_xor_sync(0xffffffffu, m0, 4));
        m1 = fmaxf(m1, __shfl_xor_sync(0xffffffffu, m1, 4));
        m0 = fmaxf(m0, __shfl_xor_sync(0xffffffffu, m0, 8));
        m1 = fmaxf(m1, __shfl_xor_sync(0xffffffffu, m1, 8));
        m0 = fmaxf(m0, __shfl_xor_sync(0xffffffffu, m0, 16));
        m1 = fmaxf(m1, __shfl_xor_sync(0xffffffffu, m1, 16));
        if (gid == 0) {
            int col = ni*8 + tig*2;
            float2 bz = *(const float2*)&b2[col];
            float o0 = fmaxf(m0 + bz.x, 0.f);
            float o1 = fmaxf(m1 + bz.y, 0.f);
            *(float2*)&out[(size_t)i*ldo + col] = make_float2(o0, o1);
            unsigned h, l; split2(o0, o1, h, l);
            oh[(size_t)i*96 + (col >> 1)] = h;
            if (SPLITLO) ol[(size_t)i*96 + (col >> 1)] = l;
        }
    }
}

// ---------------- wide-M pre-split GEMM with internal N loop ----------------
template<bool SPLITLO, int NT>
__global__ void __launch_bounds__(256, 2) hgemm_w(
        const unsigned* __restrict__ Ah_g,
        const unsigned* __restrict__ Wh_g, const unsigned* __restrict__ Wl_g,
        const float* __restrict__ bias,
        unsigned* __restrict__ Oh, unsigned* __restrict__ Ol,
        int KP, int Nd) {
    __shared__ unsigned Ahs[256*20];
    __shared__ unsigned Bhs[64*20], Bls[64*20];
    int tid  = threadIdx.x;
    int lane = tid & 31, warp = tid >> 5;
    int wm = warp & 3, wn = warp >> 2;
    int gid = lane >> 2, tig = lane & 3;
    int bm = blockIdx.y * 256;
    int NdP = Nd >> 1;

    #pragma unroll 1
    for (int nt = 0; nt < NT; nt++) {
        int bn = (blockIdx.x*NT + nt)*64;
        float acc[4][4][4] = {};
        #pragma unroll 1
        for (int k0p = 0; k0p < KP; k0p += 16) {
            uint4 ra[4], rbh, rbl;
            #pragma unroll
            for (int q = 0; q < 4; q++) {
                int e = q*256 + tid;
                int r = e >> 2, c4 = (e & 3)*4;
                ra[q] = *(const uint4*)&Ah_g[(size_t)(bm + r)*KP + k0p + c4];
            }
            {
                int r = tid >> 2, c4 = (tid & 3)*4;
                size_t go = (size_t)(bn + r)*KP + k0p + c4;
                rbh = *(const uint4*)&Wh_g[go];
                rbl = *(const uint4*)&Wl_g[go];
            }
            __syncthreads();
            #pragma unroll
            for (int q = 0; q < 4; q++) {
                int e = q*256 + tid;
                int r = e >> 2, c4 = (e & 3)*4;
                *(uint4*)&Ahs[r*20 + c4] = ra[q];
            }
            {
                int r = tid >> 2, c4 = (tid & 3)*4;
                *(uint4*)&Bhs[r*20 + c4] = rbh;
                *(uint4*)&Bls[r*20 + c4] = rbl;
            }
            __syncthreads();
            #pragma unroll
            for (int s = 0; s < 2; s++) {
                int p = s*8 + tig;
                unsigned ah[4][4];
                #pragma unroll
                for (int mi = 0; mi < 4; mi++) {
                    int r = wm*64 + mi*16 + gid;
                    ah[mi][0] = Ahs[r*20 + p];       ah[mi][1] = Ahs[(r+8)*20 + p];
                    ah[mi][2] = Ahs[r*20 + p + 4];   ah[mi][3] = Ahs[(r+8)*20 + p + 4];
                }
                #pragma unroll
                for (int ni = 0; ni < 4; ni++) {
                    int c = wn*32 + ni*8 + gid;
                    unsigned bh0 = Bhs[c*20 + p], bh1 = Bhs[c*20 + p + 4];
                    unsigned bl0 = Bls[c*20 + p], bl1 = Bls[c*20 + p + 4];
                    #pragma unroll
                    for (int mi = 0; mi < 4; mi++) {
                        MMA_F16(acc[mi][ni], ah[mi][0],ah[mi][1],ah[mi][2],ah[mi][3], bh0,bh1);
                        MMA_F16(acc[mi][ni], ah[mi][0],ah[mi][1],ah[mi][2],ah[mi][3], bl0,bl1);
                    }
                }
            }
        }
        #pragma unroll
        for (int mi = 0; mi < 4; mi++) {
            int row = bm + wm*64 + mi*16 + gid;
            #pragma unroll
            for (int ni = 0; ni < 4; ni++) {
                int col = bn + wn*32 + ni*8 + tig*2;
                float bz0 = bias[col], bz1 = bias[col+1];
                float z0 = fmaxf(acc[mi][ni][0] + bz0, 0.f);
                float z1 = fmaxf(acc[mi][ni][1] + bz1, 0.f);
                float z2 = fmaxf(acc[mi][ni][2] + bz0, 0.f);
                float z3 = fmaxf(acc[mi][ni][3] + bz1, 0.f);
                unsigned h, l;
                split2(z0, z1, h, l);
                Oh[(size_t)row*NdP + (col >> 1)] = h;
                if (SPLITLO) Ol[(size_t)row*NdP + (col >> 1)] = l;
                split2(z2, z3, h, l);
                Oh[(size_t)(row+8)*NdP + (col >> 1)] = h;
                if (SPLITLO) Ol[(size_t)(row+8)*NdP + (col >> 1)] = l;
            }
        }
    }
}

// ---------------- pre-split fp16 GEMM (3-term, small layers) ----------------
template<bool RELU, bool SPLITOUT>
__global__ void __launch_bounds__(256, 2) hgemm_ps(
        const unsigned* __restrict__ Ah_g, const unsigned* __restrict__ Al_g,
        const unsigned* __restrict__ Wh_g, const unsigned* __restrict__ Wl_g,
        const float* __restrict__ bias,
        unsigned* __restrict__ Oh, unsigned* __restrict__ Ol,
        float* __restrict__ Of, int KP, int Nd) {
    __shared__ unsigned Ahs[128*20], Als[128*20];
    __shared__ unsigned Bhs[64*20],  Bls[64*20];
    int tid  = threadIdx.x;
    int lane = tid & 31, warp = tid >> 5;
    int wm = warp & 3, wn = warp >> 2;
    int gid = lane >> 2, tig = lane & 3;
    int bm = blockIdx.y * 128, bn = blockIdx.x * 64;
    float acc[2][4][4] = {};

    for (int k0p = 0; k0p < KP; k0p += 16) {
        uint4 rah[2], ral[2], rbh, rbl;
        #pragma unroll
        for (int q = 0; q < 2; q++) {
            int e = q*256 + tid;
            int r = e >> 2, c4 = (e & 3)*4;
            size_t go = (size_t)(bm + r)*KP + k0p + c4;
            rah[q] = *(const uint4*)&Ah_g[go];
            ral[q] = *(const uint4*)&Al_g[go];
        }
        {
            int r = tid >> 2, c4 = (tid & 3)*4;
            size_t go = (size_t)(bn + r)*KP + k0p + c4;
            rbh = *(const uint4*)&Wh_g[go];
            rbl = *(const uint4*)&Wl_g[go];
        }
        __syncthreads();
        #pragma unroll
        for (int q = 0; q < 2; q++) {
            int e = q*256 + tid;
            int r = e >> 2, c4 = (e & 3)*4;
            *(uint4*)&Ahs[r*20 + c4] = rah[q];
            *(uint4*)&Als[r*20 + c4] = ral[q];
        }
        {
            int r = tid >> 2, c4 = (tid & 3)*4;
            *(uint4*)&Bhs[r*20 + c4] = rbh;
            *(uint4*)&Bls[r*20 + c4] = rbl;
        }
        __syncthreads();
        #pragma unroll
        for (int s = 0; s < 2; s++) {
            int p = s*8 + tig;
            unsigned ah[2][4], al[2][4];
            #pragma unroll
            for (int mi = 0; mi < 2; mi++) {
                int r = wm*32 + mi*16 + gid;
                ah[mi][0] = Ahs[r*20 + p];       ah[mi][1] = Ahs[(r+8)*20 + p];
                ah[mi][2] = Ahs[r*20 + p + 4];   ah[mi][3] = Ahs[(r+8)*20 + p + 4];
                al[mi][0] = Als[r*20 + p];       al[mi][1] = Als[(r+8)*20 + p];
                al[mi][2] = Als[r*20 + p + 4];   al[mi][3] = Als[(r+8)*20 + p + 4];
            }
            #pragma unroll
            for (int ni = 0; ni < 4; ni++) {
                int c = wn*32 + ni*8 + gid;
                unsigned bh0 = Bhs[c*20 + p], bh1 = Bhs[c*20 + p + 4];
                unsigned bl0 = Bls[c*20 + p], bl1 = Bls[c*20 + p + 4];
                #pragma unroll
                for (int mi = 0; mi < 2; mi++) {
                    MMA_F16(acc[mi][ni], ah[mi][0],ah[mi][1],ah[mi][2],ah[mi][3], bh0,bh1);
                    MMA_F16(acc[mi][ni], ah[mi][0],ah[mi][1],ah[mi][2],ah[mi][3], bl0,bl1);
                    MMA_F16(acc[mi][ni], al[mi][0],al[mi][1],al[mi][2],al[mi][3], bh0,bh1);
                }
            }
        }
    }
    int NdP = Nd >> 1;
    #pragma unroll
    for (int mi = 0; mi < 2; mi++) {
        int row = bm + wm*32 + mi*16 + gid;
        #pragma unroll
        for (int ni = 0; ni < 4; ni++) {
            int col = bn + wn*32 + ni*8 + tig*2;
            float bz0 = bias[col], bz1 = bias[col+1];
            float z0 = acc[mi][ni][0] + bz0;
            float z1 = acc[mi][ni][1] + bz1;
            float z2 = acc[mi][ni][2] + bz0;
            float z3 = acc[mi][ni][3] + bz1;
            if (RELU) {
                z0 = fmaxf(z0, 0.f); z1 = fmaxf(z1, 0.f);
                z2 = fmaxf(z2, 0.f); z3 = fmaxf(z3, 0.f);
            }
            if (SPLITOUT) {
                unsigned h, l;
                split2(z0, z1, h, l);
                Oh[(size_t)row*NdP + (col >> 1)] = h;
                Ol[(size_t)row*NdP + (col >> 1)] = l;
                split2(z2, z3, h, l);
                Oh[(size_t)(row+8)*NdP + (col >> 1)] = h;
                Ol[(size_t)(row+8)*NdP + (col >> 1)] = l;
            } else {
                *(float2*)&Of[(size_t)row*Nd + col]     = make_float2(z0, z1);
                *(float2*)&Of[(size_t)(row+8)*Nd + col] = make_float2(z2, z3);
            }
        }
    }
}

// ---------------- host orchestration ----------------
template<int F, bool EAL>
static void run_conv(const float* xp, int ldx,
                     const unsigned* xh, const unsigned* xl, int strideP, int offP,
                     const float* w1, const float* b1,
                     const float* w2, const float* b2,
                     float* outp, unsigned* oh, unsigned* ol) {
    precompute_k<F><<<(NPT*DIM)/256, 256>>>(xp, ldx, w1, b1);
    distmma_k<F><<<dim3(PTS/64, PTS/128, NG), 256>>>(xh, xl, strideP, offP);
    topk_k<<<NPT/8, 256>>>();
    w2prep_k<<<8, 256>>>(w2);
    edgeconv_k<EAL, EAL><<<NPT/4, 128>>>(b2, outp, 192, oh, ol);
}

extern "C" void kernel_launch(void* const* d_in, const int* in_sizes, int n_in,
                              void* d_out, int out_size) {
    const float* x    = (const float*)d_in[0];
    const float* c1w1 = (const float*)d_in[2];
    const float* c1b1 = (const float*)d_in[3];
    const float* c1w2 = (const float*)d_in[4];
    const float* c1b2 = (const float*)d_in[5];
    const float* c2w1 = (const float*)d_in[6];
    const float* c2b1 = (const float*)d_in[7];
    const float* c2w2 = (const float*)d_in[8];
    const float* c2b2 = (const float*)d_in[9];
    const float* c3w1 = (const float*)d_in[10];
    const float* c3b1 = (const float*)d_in[11];
    const float* c3w2 = (const float*)d_in[12];
    const float* c3b2 = (const float*)d_in[13];
    const float* lw   = (const float*)d_in[14];
    const float* lb   = (const float*)d_in[15];
    const float* hw1  = (const float*)d_in[16];
    const float* hb1  = (const float*)d_in[17];
    const float* hw2  = (const float*)d_in[18];
    const float* hb2  = (const float*)d_in[19];
    const float* hw3  = (const float*)d_in[20];
    const float* hb3  = (const float*)d_in[21];
    float* out = (float*)d_out;

    float *hcat, *big, *h1b, *h2b;
    unsigned *x1h, *x1l, *ah0, *al0;
    unsigned *wlh, *wll, *w1h, *w1l, *w2h, *w2l, *w3h, *w3l;
    cudaGetSymbolAddress((void**)&hcat, g_hcat);
    cudaGetSymbolAddress((void**)&big,  g_big);
    cudaGetSymbolAddress((void**)&h1b,  g_h1);
    cudaGetSymbolAddress((void**)&h2b,  g_h2);
    cudaGetSymbolAddress((void**)&x1h,  g_x1h);
    cudaGetSymbolAddress((void**)&x1l,  g_x1l);
    cudaGetSymbolAddress((void**)&ah0,  g_ah0);
    cudaGetSymbolAddress((void**)&al0,  g_al0);
    cudaGetSymbolAddress((void**)&wlh,  g_wlh);
    cudaGetSymbolAddress((void**)&wll,  g_wll);
    cudaGetSymbolAddress((void**)&w1h,  g_hw1h);
    cudaGetSymbolAddress((void**)&w1l,  g_hw1l);
    cudaGetSymbolAddress((void**)&w2h,  g_hw2h);
    cudaGetSymbolAddress((void**)&w2l,  g_hw2l);
    cudaGetSymbolAddress((void**)&w3h,  g_hw3h);
    cudaGetSymbolAddress((void**)&w3l,  g_hw3l);

    unsigned* a1h = (unsigned*)big;  unsigned* a1l = a1h + (size_t)NPT*512;
    unsigned* a2h = (unsigned*)h1b;  unsigned* a2l = a2h + (size_t)NPT*128;
    unsigned* a3h = (unsigned*)h2b;  unsigned* a3l = a3h + (size_t)NPT*64;

    splitx1_k<<<(NPT*8)/256, 256>>>(x);

    run_conv<14, true >(x,         14,  x1h, x1l, 8,  0,  c1w1, c1b1, c1w2, c1b2,
                        hcat,       ah0,      al0);
    run_conv<64, true >(hcat,      192, ah0, al0, 96, 0,  c2w1, c2b1, c2w2, c2b2,
                        hcat + 64,  ah0 + 32, al0 + 32);
    run_conv<64, false>(hcat + 64, 192, ah0, al0, 96, 32, c3w1, c3b1, c3w2, c3b2,
                        hcat + 128, ah0 + 64, al0 + 64);

    // coalesced weight prep (32x32 smem transpose tiles)
    wprep_k<<<dim3(96/32,  1024/32), 256>>>(lw,  wlh, wll, 192,  1024);
    wprep_k<<<dim3(512/32, 256/32),  256>>>(hw1, w1h, w1l, 1024, 256);
    wprep_k<<<dim3(128/32, 128/32),  256>>>(hw2, w2h, w2l, 256,  128);
    wprep_k<<<dim3(64/32,  64/32),   256>>>(hw3, w3h, w3l, 128,  64);

    hgemm_w<false, 4><<<dim3(4, 128), 256>>>(ah0, wlh, wll, lb,  a1h, nullptr, 96,  1024);
    hgemm_w<true,  2><<<dim3(2, 128), 256>>>(a1h, w1h, w1l, hb1, a2h, a2l,     512, 256);
    hgemm_ps<true,  true ><<<dim3(2, 256), 256>>>(a2h, a2l, w2h, w2l, hb2, a3h, a3l, nullptr, 128, 128);
    hgemm_ps<false, false><<<dim3(1, 256), 256>>>(a3h, a3l, w3h, w3l, hb3, nullptr, nullptr, out, 64, 64);
}

// round 16
// speedup vs baseline: 1.1717x; 1.0481x over previous
#include <cuda_runtime.h>
#include <cuda_fp16.h>
#include <cstdint>
#include <cstddef>
#include <math.h>
#include <float.h>

#define NG   32
#define PTS  1024
#define NPT  (NG*PTS)      // 32768
#define KNB  30
#define DIM  64

// ---------------- device scratch (static, no allocations) ----------------
__device__ float g_s[NPT];
__device__ int   g_idx[NPT*KNB];
__device__ float g_B[NPT*DIM];
__device__ float g_C[NPT*DIM];
__device__ float g_hcat[NPT*192];
__device__ float g_big[(size_t)NPT*1024];   // dist matrix; later a1h/a1l split buffers
__device__ float g_h1[NPT*256];             // later a2h/a2l
__device__ float g_h2[NPT*128];             // later a3h/a3l
__device__ unsigned g_w2h[64*32];
__device__ unsigned g_w2l[64*32];
__device__ unsigned g_x1h[NPT*8],  g_x1l[NPT*8];
__device__ unsigned g_ah0[NPT*96], g_al0[NPT*96];
__device__ unsigned g_wlh[1024*96],  g_wll[1024*96];
__device__ unsigned g_hw1h[256*512], g_hw1l[256*512];
__device__ unsigned g_hw2h[128*128], g_hw2l[128*128];
__device__ unsigned g_hw3h[64*64],   g_hw3l[64*64];

// ---------------- fp16 split helpers ----------------
__device__ __forceinline__ void split2(float x, float y, unsigned& h, unsigned& l) {
    __half2 p = __floats2half2_rn(x, y);
    h = *reinterpret_cast<unsigned*>(&p);
    float rx = x - __low2float(p);
    float ry = y - __high2float(p);
    __half2 q = __floats2half2_rn(rx, ry);
    l = *reinterpret_cast<unsigned*>(&q);
}

#define MMA_F16(d, a0,a1,a2,a3, b0,b1) \
    asm volatile("mma.sync.aligned.m16n8k16.row.col.f32.f16.f16.f32 " \
        "{%0,%1,%2,%3}, {%4,%5,%6,%7}, {%8,%9}, {%0,%1,%2,%3};" \
        : "+f"(d[0]),"+f"(d[1]),"+f"(d[2]),"+f"(d[3]) \
        : "r"(a0),"r"(a1),"r"(a2),"r"(a3), "r"(b0),"r"(b1))

// ---------------- prep kernels ----------------
__global__ void splitx1_k(const float* __restrict__ x) {
    int e = blockIdx.x*256 + threadIdx.x;
    int i = e >> 3, p = e & 7;
    float v0 = 0.f, v1 = 0.f;
    if (p < 7) { v0 = x[i*14 + 2*p]; v1 = x[i*14 + 2*p + 1]; }
    unsigned h, l; split2(v0, v1, h, l);
    g_x1h[e] = h; g_x1l[e] = l;
}

// coalesced transpose-split: W [K][N] fp32 -> Wh/Wl [N][KP] fp16-pair words.
__global__ void wprep_k(const float* __restrict__ W, unsigned* __restrict__ Wh,
                        unsigned* __restrict__ Wl, int K, int N) {
    __shared__ unsigned th[32][33], tl[32][33];
    int KP = K >> 1;
    int tp0 = blockIdx.x*32, tn0 = blockIdx.y*32;
    int tx = threadIdx.x & 31, ty4 = (threadIdx.x >> 5)*4;
    #pragma unroll
    for (int q = 0; q < 4; q++) {
        int p = tp0 + ty4 + q;
        float w0 = W[(size_t)(2*p)*N + tn0 + tx];
        float w1 = W[(size_t)(2*p + 1)*N + tn0 + tx];
        unsigned h, l; split2(w0, w1, h, l);
        th[ty4 + q][tx] = h;
        tl[ty4 + q][tx] = l;
    }
    __syncthreads();
    #pragma unroll
    for (int q = 0; q < 4; q++) {
        int n = tn0 + ty4 + q;
        Wh[(size_t)n*KP + tp0 + tx] = th[tx][ty4 + q];
        Wl[(size_t)n*KP + tp0 + tx] = tl[tx][ty4 + q];
    }
}

// ---------------- pairwise distances (pre-split fp16 3-term mma) ----------------
template<int F>
__global__ void __launch_bounds__(256, 2) distmma_k(
        const unsigned* __restrict__ Xh, const unsigned* __restrict__ Xl,
        int strideP, int offP) {
    constexpr int PAIRS = ((F + 15)/16)*8;
    constexpr int STR   = PAIRS + 4;
    __shared__ unsigned Ah[128*STR], Al[128*STR];
    __shared__ unsigned Bh[64*STR],  Bl[64*STR];
    int g  = blockIdx.z;
    int bm = blockIdx.y*128, bn = blockIdx.x*64;
    int tid = threadIdx.x, lane = tid & 31, warp = tid >> 5;
    int wm = warp & 3, wn = warp >> 2;
    int gid = lane >> 2, tig = lane & 3;
    int base = g*PTS;

    for (int e = tid; e < 32*PAIRS; e += 256) {
        int r = e / (PAIRS/4), c4 = (e % (PAIRS/4))*4;
        size_t go = (size_t)(base + bm + r)*strideP + offP + c4;
        *(uint4*)&Ah[r*STR + c4] = *(const uint4*)&Xh[go];
        *(uint4*)&Al[r*STR + c4] = *(const uint4*)&Xl[go];
    }
    for (int e = tid; e < 16*PAIRS; e += 256) {
        int r = e / (PAIRS/4), c4 = (e % (PAIRS/4))*4;
        size_t go = (size_t)(base + bn + r)*strideP + offP + c4;
        *(uint4*)&Bh[r*STR + c4] = *(const uint4*)&Xh[go];
        *(uint4*)&Bl[r*STR + c4] = *(const uint4*)&Xl[go];
    }
    __syncthreads();

    float acc[2][4][4] = {};
    #pragma unroll
    for (int s = 0; s < PAIRS/8; s++) {
        int p = s*8 + tig;
        unsigned ah[2][4], al[2][4];
        #pragma unroll
        for (int mi = 0; mi < 2; mi++) {
            int r = wm*32 + mi*16 + gid;
            ah[mi][0] = Ah[r*STR + p];       ah[mi][1] = Ah[(r+8)*STR + p];
            ah[mi][2] = Ah[r*STR + p + 4];   ah[mi][3] = Ah[(r+8)*STR + p + 4];
            al[mi][0] = Al[r*STR + p];       al[mi][1] = Al[(r+8)*STR + p];
            al[mi][2] = Al[r*STR + p + 4];   al[mi][3] = Al[(r+8)*STR + p + 4];
        }
        #pragma unroll
        for (int ni = 0; ni < 4; ni++) {
            int c = wn*32 + ni*8 + gid;
            unsigned bh0 = Bh[c*STR + p], bh1 = Bh[c*STR + p + 4];
            unsigned bl0 = Bl[c*STR + p], bl1 = Bl[c*STR + p + 4];
            #pragma unroll
            for (int mi = 0; mi < 2; mi++) {
                MMA_F16(acc[mi][ni], ah[mi][0],ah[mi][1],ah[mi][2],ah[mi][3], bh0,bh1);
                MMA_F16(acc[mi][ni], ah[mi][0],ah[mi][1],ah[mi][2],ah[mi][3], bl0,bl1);
                MMA_F16(acc[mi][ni], al[mi][0],al[mi][1],al[mi][2],al[mi][3], bh0,bh1);
            }
        }
    }
    #pragma unroll
    for (int mi = 0; mi < 2; mi++) {
        int row = bm + wm*32 + mi*16 + gid;
        float si0 = g_s[base + row];
        float si1 = g_s[base + row + 8];
        #pragma unroll
        for (int ni = 0; ni < 4; ni++) {
            int col = bn + wn*32 + ni*8 + 2*tig;
            float sj0 = g_s[base + col];
            float sj1 = g_s[base + col + 1];
            float2 o0 = make_float2(si0 + sj0 - 2.f*acc[mi][ni][0],
                                    si0 + sj1 - 2.f*acc[mi][ni][1]);
            float2 o1 = make_float2(si1 + sj0 - 2.f*acc[mi][ni][2],
                                    si1 + sj1 - 2.f*acc[mi][ni][3]);
            *(float2*)&g_big[(size_t)(base + row)*PTS + col]     = o0;
            *(float2*)&g_big[(size_t)(base + row + 8)*PTS + col] = o1;
        }
    }
}

// ---------------- top-K selection (u64 key top-3 cache; smem backing; exact) ----
// key = (monotone_u32(d) << 6) | (slot+1): strictly ordered by (d, slot), unique.
// Candidate values live in SHARED memory (not registers) — init builds the top-3
// cache from in-flight loads; rescans (rare, ~0.5/warp) read back from smem.
__global__ void __launch_bounds__(256) topk_k() {
    __shared__ unsigned sd[8][1024];    // [warp][t*32 + lane]
    int w = threadIdx.x >> 5, lane = threadIdx.x & 31;
    int i = blockIdx.x*8 + w;
    int g = i >> 10;
    const float* row = &g_big[(size_t)i*PTS];
    unsigned* sdw = sd[w];

    unsigned long long k1 = ~0ull, k2 = ~0ull, k3 = ~0ull;
    #pragma unroll
    for (int t = 0; t < 32; t++) {
        int b = __float_as_int(row[lane + 32*t]);
        unsigned d = (unsigned)b ^ (0x80000000u | (unsigned)(b >> 31));  // monotone
        sdw[t*32 + lane] = d;
        unsigned long long key = ((unsigned long long)d << 6) | (unsigned)(t + 1);
        if (key < k1)      { k3 = k2; k2 = k1; k1 = key; }
        else if (key < k2) { k3 = k2; k2 = key; }
        else if (key < k3) { k3 = key; }
    }
    __syncwarp();

    unsigned long long lastk = 0ull;
    for (int kk = 0; kk < KNB; kk++) {
        unsigned m1 = (unsigned)(k1 >> 6);
        unsigned umin = __reduce_min_sync(0xffffffffu, m1);
        int t1 = (int)(k1 & 63) - 1;
        unsigned myjv = (m1 == umin) ? (unsigned)(lane + 32*t1) : 0xFFFFFFFFu;
        unsigned jv = __reduce_min_sync(0xffffffffu, myjv);
        if (lane == 0) g_idx[(size_t)i*KNB + kk] = (g << 10) + (int)jv;
        if ((jv & 31) == lane) {
            lastk = k1;
            k1 = k2; k2 = k3; k3 = ~0ull;
            if (k1 == ~0ull) {                 // cache drained: rescan > lastk
                k2 = ~0ull; k3 = ~0ull;
                #pragma unroll 4
                for (int t = 0; t < 32; t++) {
                    unsigned long long key =
                        ((unsigned long long)sdw[t*32 + lane] << 6) | (unsigned)(t + 1);
                    if (key > lastk) {
                        if (key < k1)      { k3 = k2; k2 = k1; k1 = key; }
                        else if (key < k2) { k3 = k2; k2 = key; }
                        else if (key < k3) { k3 = key; }
                    }
                }
            }
        }
    }
}

// ---------------- precompute B/C (+ squared norms fused) ----------------
template<int F>
__global__ void precompute_k(const float* __restrict__ x, int ldx,
                             const float* __restrict__ W1, const float* __restrict__ b1) {
    int gid = blockIdx.x*256 + threadIdx.x;
    int i = gid >> 6, c = gid & 63;
    const float* xr = x + (size_t)i*ldx;
    float a = 0.f, b = 0.f, s = 0.f;
    #pragma unroll
    for (int f = 0; f < F; f++) {
        float xv = xr[f];
        a += xv * W1[f*DIM + c];
        b += xv * W1[(F + f)*DIM + c];
        s += xv * xv;
    }
    g_B[gid] = b;
    g_C[gid] = a - b + b1[c];
    if (c == 0) g_s[i] = s;
}

// ---------------- edgeconv W2 prep ----------------
__global__ void w2prep_k(const float* __restrict__ W2) {
    int e = blockIdx.x*256 + threadIdx.x;
    int n = e & 63, j = e >> 6;
    float w0 = W2[(2*j)*64 + n];
    float w1 = W2[(2*j+1)*64 + n];
    unsigned h, l; split2(w0, w1, h, l);
    g_w2h[n*32 + j] = h;
    g_w2l[n*32 + j] = l;
}

// ---------------- edgeconv ----------------
template<bool AL, bool SPLITLO>
__global__ void __launch_bounds__(128) edgeconv_k(
        const float* __restrict__ b2, float* __restrict__ out, int ldo,
        unsigned* __restrict__ oh, unsigned* __restrict__ ol) {
    __shared__ unsigned Hh[4][32][36];
    __shared__ unsigned Hl[4][32][36];
    int tid = threadIdx.x, lane = tid & 31, warp = tid >> 5;
    int gid = lane >> 2, tig = lane & 3;
    int i = blockIdx.x*4 + warp;

    unsigned (*hh)[36] = Hh[warp];
    unsigned (*hl)[36] = Hl[warp];
    const int* idxr = g_idx + (size_t)i*KNB;
    float2 cv = *(const float2*)&g_C[(size_t)i*DIM + 2*lane];
    #pragma unroll
    for (int k = 0; k < 32; k++) {
        int j = idxr[(k < KNB) ? k : 0];
        float2 bv = *(const float2*)&g_B[(size_t)j*DIM + 2*lane];
        float f0 = fmaxf(cv.x + bv.x, 0.f);
        float f1 = fmaxf(cv.y + bv.y, 0.f);
        unsigned h, l; split2(f0, f1, h, l);
        hh[k][lane] = h;
        if (AL) hl[k][lane] = l;
    }
    __syncwarp();

    float acc[2][8][4] = {};
    #pragma unroll
    for (int s = 0; s < 4; s++) {
        int p = s*8 + tig;
        unsigned ah[2][4], al[2][4];
        #pragma unroll
        for (int mi = 0; mi < 2; mi++) {
            int r = mi*16 + gid;
            ah[mi][0] = hh[r][p];   ah[mi][1] = hh[r+8][p];
            ah[mi][2] = hh[r][p+4]; ah[mi][3] = hh[r+8][p+4];
            if (AL) {
                al[mi][0] = hl[r][p];   al[mi][1] = hl[r+8][p];
                al[mi][2] = hl[r][p+4]; al[mi][3] = hl[r+8][p+4];
            }
        }
        #pragma unroll
        for (int ni = 0; ni < 8; ni++) {
            int c = ni*8 + gid;
            unsigned bh0 = g_w2h[c*32 + p], bh1 = g_w2h[c*32 + p + 4];
            unsigned bl0 = g_w2l[c*32 + p], bl1 = g_w2l[c*32 + p + 4];
            #pragma unroll
            for (int mi = 0; mi < 2; mi++) {
                MMA_F16(acc[mi][ni], ah[mi][0],ah[mi][1],ah[mi][2],ah[mi][3], bh0,bh1);
                MMA_F16(acc[mi][ni], ah[mi][0],ah[mi][1],ah[mi][2],ah[mi][3], bl0,bl1);
                if (AL)
                    MMA_F16(acc[mi][ni], al[mi][0],al[mi][1],al[mi][2],al[mi][3], bh0,bh1);
            }
        }
    }
    #pragma unroll
    for (int ni = 0; ni < 8; ni++) {
        float m0 = fmaxf(fmaxf(acc[0][ni][0], acc[0][ni][2]),
                         fmaxf(acc[1][ni][0], acc[1][ni][2]));
        float m1 = fmaxf(fmaxf(acc[0][ni][1], acc[0][ni][3]),
                         fmaxf(acc[1][ni][1], acc[1][ni][3]));
        m0 = fmaxf(m0, __shfl_xor_sync(0xffffffffu, m0, 4));
        m1 = fmaxf(m1, __shfl_xor_sync(0xffffffffu, m1, 4));
        m0 = fmaxf(m0, __shfl_xor_sync(0xffffffffu, m0, 8));
        m1 = fmaxf(m1, __shfl_xor_sync(0xffffffffu, m1, 8));
        m0 = fmaxf(m0, __shfl_xor_sync(0xffffffffu, m0, 16));
        m1 = fmaxf(m1, __shfl_xor_sync(0xffffffffu, m1, 16));
        if (gid == 0) {
            int col = ni*8 + tig*2;
            float2 bz = *(const float2*)&b2[col];
            float o0 = fmaxf(m0 + bz.x, 0.f);
            float o1 = fmaxf(m1 + bz.y, 0.f);
            *(float2*)&out[(size_t)i*ldo + col] = make_float2(o0, o1);
            unsigned h, l; split2(o0, o1, h, l);
            oh[(size_t)i*96 + (col >> 1)] = h;
            if (SPLITLO) ol[(size_t)i*96 + (col >> 1)] = l;
        }
    }
}

// ---------------- wide-M pre-split GEMM with internal N loop ----------------
template<bool SPLITLO, int NT>
__global__ void __launch_bounds__(256, 2) hgemm_w(
        const unsigned* __restrict__ Ah_g,
        const unsigned* __restrict__ Wh_g, const unsigned* __restrict__ Wl_g,
        const float* __restrict__ bias,
        unsigned* __restrict__ Oh, unsigned* __restrict__ Ol,
        int KP, int Nd) {
    __shared__ unsigned Ahs[256*20];
    __shared__ unsigned Bhs[64*20], Bls[64*20];
    int tid  = threadIdx.x;
    int lane = tid & 31, warp = tid >> 5;
    int wm = warp & 3, wn = warp >> 2;
    int gid = lane >> 2, tig = lane & 3;
    int bm = blockIdx.y * 256;
    int NdP = Nd >> 1;

    #pragma unroll 1
    for (int nt = 0; nt < NT; nt++) {
        int bn = (blockIdx.x*NT + nt)*64;
        float acc[4][4][4] = {};
        #pragma unroll 1
        for (int k0p = 0; k0p < KP; k0p += 16) {
            uint4 ra[4], rbh, rbl;
            #pragma unroll
            for (int q = 0; q < 4; q++) {
                int e = q*256 + tid;
                int r = e >> 2, c4 = (e & 3)*4;
                ra[q] = *(const uint4*)&Ah_g[(size_t)(bm + r)*KP + k0p + c4];
            }
            {
                int r = tid >> 2, c4 = (tid & 3)*4;
                size_t go = (size_t)(bn + r)*KP + k0p + c4;
                rbh = *(const uint4*)&Wh_g[go];
                rbl = *(const uint4*)&Wl_g[go];
            }
            __syncthreads();
            #pragma unroll
            for (int q = 0; q < 4; q++) {
                int e = q*256 + tid;
                int r = e >> 2, c4 = (e & 3)*4;
                *(uint4*)&Ahs[r*20 + c4] = ra[q];
            }
            {
                int r = tid >> 2, c4 = (tid & 3)*4;
                *(uint4*)&Bhs[r*20 + c4] = rbh;
                *(uint4*)&Bls[r*20 + c4] = rbl;
            }
            __syncthreads();
            #pragma unroll
            for (int s = 0; s < 2; s++) {
                int p = s*8 + tig;
                unsigned ah[4][4];
                #pragma unroll
                for (int mi = 0; mi < 4; mi++) {
                    int r = wm*64 + mi*16 + gid;
                    ah[mi][0] = Ahs[r*20 + p];       ah[mi][1] = Ahs[(r+8)*20 + p];
                    ah[mi][2] = Ahs[r*20 + p + 4];   ah[mi][3] = Ahs[(r+8)*20 + p + 4];
                }
                #pragma unroll
                for (int ni = 0; ni < 4; ni++) {
                    int c = wn*32 + ni*8 + gid;
                    unsigned bh0 = Bhs[c*20 + p], bh1 = Bhs[c*20 + p + 4];
                    unsigned bl0 = Bls[c*20 + p], bl1 = Bls[c*20 + p + 4];
                    #pragma unroll
                    for (int mi = 0; mi < 4; mi++) {
                        MMA_F16(acc[mi][ni], ah[mi][0],ah[mi][1],ah[mi][2],ah[mi][3], bh0,bh1);
                        MMA_F16(acc[mi][ni], ah[mi][0],ah[mi][1],ah[mi][2],ah[mi][3], bl0,bl1);
                    }
                }
            }
        }
        #pragma unroll
        for (int mi = 0; mi < 4; mi++) {
            int row = bm + wm*64 + mi*16 + gid;
            #pragma unroll
            for (int ni = 0; ni < 4; ni++) {
                int col = bn + wn*32 + ni*8 + tig*2;
                float bz0 = bias[col], bz1 = bias[col+1];
                float z0 = fmaxf(acc[mi][ni][0] + bz0, 0.f);
                float z1 = fmaxf(acc[mi][ni][1] + bz1, 0.f);
                float z2 = fmaxf(acc[mi][ni][2] + bz0, 0.f);
                float z3 = fmaxf(acc[mi][ni][3] + bz1, 0.f);
                unsigned h, l;
                split2(z0, z1, h, l);
                Oh[(size_t)row*NdP + (col >> 1)] = h;
                if (SPLITLO) Ol[(size_t)row*NdP + (col >> 1)] = l;
                split2(z2, z3, h, l);
                Oh[(size_t)(row+8)*NdP + (col >> 1)] = h;
                if (SPLITLO) Ol[(size_t)(row+8)*NdP + (col >> 1)] = l;
            }
        }
    }
}

// ---------------- pre-split fp16 GEMM (3-term, small layers) ----------------
template<bool RELU, bool SPLITOUT>
__global__ void __launch_bounds__(256, 2) hgemm_ps(
        const unsigned* __restrict__ Ah_g, const unsigned* __restrict__ Al_g,
        const unsigned* __restrict__ Wh_g, const unsigned* __restrict__ Wl_g,
        const float* __restrict__ bias,
        unsigned* __restrict__ Oh, unsigned* __restrict__ Ol,
        float* __restrict__ Of, int KP, int Nd) {
    __shared__ unsigned Ahs[128*20], Als[128*20];
    __shared__ unsigned Bhs[64*20],  Bls[64*20];
    int tid  = threadIdx.x;
    int lane = tid & 31, warp = tid >> 5;
    int wm = warp & 3, wn = warp >> 2;
    int gid = lane >> 2, tig = lane & 3;
    int bm = blockIdx.y * 128, bn = blockIdx.x * 64;
    float acc[2][4][4] = {};

    for (int k0p = 0; k0p < KP; k0p += 16) {
        uint4 rah[2], ral[2], rbh, rbl;
        #pragma unroll
        for (int q = 0; q < 2; q++) {
            int e = q*256 + tid;
            int r = e >> 2, c4 = (e & 3)*4;
            size_t go = (size_t)(bm + r)*KP + k0p + c4;
            rah[q] = *(const uint4*)&Ah_g[go];
            ral[q] = *(const uint4*)&Al_g[go];
        }
        {
            int r = tid >> 2, c4 = (tid & 3)*4;
            size_t go = (size_t)(bn + r)*KP + k0p + c4;
            rbh = *(const uint4*)&Wh_g[go];
            rbl = *(const uint4*)&Wl_g[go];
        }
        __syncthreads();
        #pragma unroll
        for (int q = 0; q < 2; q++) {
            int e = q*256 + tid;
            int r = e >> 2, c4 = (e & 3)*4;
            *(uint4*)&Ahs[r*20 + c4] = rah[q];
            *(uint4*)&Als[r*20 + c4] = ral[q];
        }
        {
            int r = tid >> 2, c4 = (tid & 3)*4;
            *(uint4*)&Bhs[r*20 + c4] = rbh;
            *(uint4*)&Bls[r*20 + c4] = rbl;
        }
        __syncthreads();
        #pragma unroll
        for (int s = 0; s < 2; s++) {
            int p = s*8 + tig;
            unsigned ah[2][4], al[2][4];
            #pragma unroll
            for (int mi = 0; mi < 2; mi++) {
                int r = wm*32 + mi*16 + gid;
                ah[mi][0] = Ahs[r*20 + p];       ah[mi][1] = Ahs[(r+8)*20 + p];
                ah[mi][2] = Ahs[r*20 + p + 4];   ah[mi][3] = Ahs[(r+8)*20 + p + 4];
                al[mi][0] = Als[r*20 + p];       al[mi][1] = Als[(r+8)*20 + p];
                al[mi][2] = Als[r*20 + p + 4];   al[mi][3] = Als[(r+8)*20 + p + 4];
            }
            #pragma unroll
            for (int ni = 0; ni < 4; ni++) {
                int c = wn*32 + ni*8 + gid;
                unsigned bh0 = Bhs[c*20 + p], bh1 = Bhs[c*20 + p + 4];
                unsigned bl0 = Bls[c*20 + p], bl1 = Bls[c*20 + p + 4];
                #pragma unroll
                for (int mi = 0; mi < 2; mi++) {
                    MMA_F16(acc[mi][ni], ah[mi][0],ah[mi][1],ah[mi][2],ah[mi][3], bh0,bh1);
                    MMA_F16(acc[mi][ni], ah[mi][0],ah[mi][1],ah[mi][2],ah[mi][3], bl0,bl1);
                    MMA_F16(acc[mi][ni], al[mi][0],al[mi][1],al[mi][2],al[mi][3], bh0,bh1);
                }
            }
        }
    }
    int NdP = Nd >> 1;
    #pragma unroll
    for (int mi = 0; mi < 2; mi++) {
        int row = bm + wm*32 + mi*16 + gid;
        #pragma unroll
        for (int ni = 0; ni < 4; ni++) {
            int col = bn + wn*32 + ni*8 + tig*2;
            float bz0 = bias[col], bz1 = bias[col+1];
            float z0 = acc[mi][ni][0] + bz0;
            float z1 = acc[mi][ni][1] + bz1;
            float z2 = acc[mi][ni][2] + bz0;
            float z3 = acc[mi][ni][3] + bz1;
            if (RELU) {
                z0 = fmaxf(z0, 0.f); z1 = fmaxf(z1, 0.f);
                z2 = fmaxf(z2, 0.f); z3 = fmaxf(z3, 0.f);
            }
            if (SPLITOUT) {
                unsigned h, l;
                split2(z0, z1, h, l);
                Oh[(size_t)row*NdP + (col >> 1)] = h;
                Ol[(size_t)row*NdP + (col >> 1)] = l;
                split2(z2, z3, h, l);
                Oh[(size_t)(row+8)*NdP + (col >> 1)] = h;
                Ol[(size_t)(row+8)*NdP + (col >> 1)] = l;
            } else {
                *(float2*)&Of[(size_t)row*Nd + col]     = make_float2(z0, z1);
                *(float2*)&Of[(size_t)(row+8)*Nd + col] = make_float2(z2, z3);
            }
        }
    }
}

// ---------------- host orchestration ----------------
template<int F, bool EAL>
static void run_conv(const float* xp, int ldx,
                     const unsigned* xh, const unsigned* xl, int strideP, int offP,
                     const float* w1, const float* b1,
                     const float* w2, const float* b2,
                     float* outp, unsigned* oh, unsigned* ol) {
    precompute_k<F><<<(NPT*DIM)/256, 256>>>(xp, ldx, w1, b1);
    distmma_k<F><<<dim3(PTS/64, PTS/128, NG), 256>>>(xh, xl, strideP, offP);
    topk_k<<<NPT/8, 256>>>();
    w2prep_k<<<8, 256>>>(w2);
    edgeconv_k<EAL, EAL><<<NPT/4, 128>>>(b2, outp, 192, oh, ol);
}

extern "C" void kernel_launch(void* const* d_in, const int* in_sizes, int n_in,
                              void* d_out, int out_size) {
    const float* x    = (const float*)d_in[0];
    const float* c1w1 = (const float*)d_in[2];
    const float* c1b1 = (const float*)d_in[3];
    const float* c1w2 = (const float*)d_in[4];
    const float* c1b2 = (const float*)d_in[5];
    const float* c2w1 = (const float*)d_in[6];
    const float* c2b1 = (const float*)d_in[7];
    const float* c2w2 = (const float*)d_in[8];
    const float* c2b2 = (const float*)d_in[9];
    const float* c3w1 = (const float*)d_in[10];
    const float* c3b1 = (const float*)d_in[11];
    const float* c3w2 = (const float*)d_in[12];
    const float* c3b2 = (const float*)d_in[13];
    const float* lw   = (const float*)d_in[14];
    const float* lb   = (const float*)d_in[15];
    const float* hw1  = (const float*)d_in[16];
    const float* hb1  = (const float*)d_in[17];
    const float* hw2  = (const float*)d_in[18];
    const float* hb2  = (const float*)d_in[19];
    const float* hw3  = (const float*)d_in[20];
    const float* hb3  = (const float*)d_in[21];
    float* out = (float*)d_out;

    float *hcat, *big, *h1b, *h2b;
    unsigned *x1h, *x1l, *ah0, *al0;
    unsigned *wlh, *wll, *w1h, *w1l, *w2h, *w2l, *w3h, *w3l;
    cudaGetSymbolAddress((void**)&hcat, g_hcat);
    cudaGetSymbolAddress((void**)&big,  g_big);
    cudaGetSymbolAddress((void**)&h1b,  g_h1);
    cudaGetSymbolAddress((void**)&h2b,  g_h2);
    cudaGetSymbolAddress((void**)&x1h,  g_x1h);
    cudaGetSymbolAddress((void**)&x1l,  g_x1l);
    cudaGetSymbolAddress((void**)&ah0,  g_ah0);
    cudaGetSymbolAddress((void**)&al0,  g_al0);
    cudaGetSymbolAddress((void**)&wlh,  g_wlh);
    cudaGetSymbolAddress((void**)&wll,  g_wll);
    cudaGetSymbolAddress((void**)&w1h,  g_hw1h);
    cudaGetSymbolAddress((void**)&w1l,  g_hw1l);
    cudaGetSymbolAddress((void**)&w2h,  g_hw2h);
    cudaGetSymbolAddress((void**)&w2l,  g_hw2l);
    cudaGetSymbolAddress((void**)&w3h,  g_hw3h);
    cudaGetSymbolAddress((void**)&w3l,  g_hw3l);

    unsigned* a1h = (unsigned*)big;  unsigned* a1l = a1h + (size_t)NPT*512;
    unsigned* a2h = (unsigned*)h1b;  unsigned* a2l = a2h + (size_t)NPT*128;
    unsigned* a3h = (unsigned*)h2b;  unsigned* a3l = a3h + (size_t)NPT*64;

    splitx1_k<<<(NPT*8)/256, 256>>>(x);

    run_conv<14, true >(x,         14,  x1h, x1l, 8,  0,  c1w1, c1b1, c1w2, c1b2,
                        hcat,       ah0,      al0);
    run_conv<64, true >(hcat,      192, ah0, al0, 96, 0,  c2w1, c2b1, c2w2, c2b2,
                        hcat + 64,  ah0 + 32, al0 + 32);
    run_conv<64, false>(hcat + 64, 192, ah0, al0, 96, 32, c3w1, c3b1, c3w2, c3b2,
                        hcat + 128, ah0 + 64, al0 + 64);

    // coalesced weight prep (32x32 smem transpose tiles)
    wprep_k<<<dim3(96/32,  1024/32), 256>>>(lw,  wlh, wll, 192,  1024);
    wprep_k<<<dim3(512/32, 256/32),  256>>>(hw1, w1h, w1l, 1024, 256);
    wprep_k<<<dim3(128/32, 128/32),  256>>>(hw2, w2h, w2l, 256,  128);
    wprep_k<<<dim3(64/32,  64/32),   256>>>(hw3, w3h, w3l, 128,  64);

    hgemm_w<false, 4><<<dim3(4, 128), 256>>>(ah0, wlh, wll, lb,  a1h, nullptr, 96,  1024);
    hgemm_w<true,  2><<<dim3(2, 128), 256>>>(a1h, w1h, w1l, hb1, a2h, a2l,     512, 256);
    hgemm_ps<true,  true ><<<dim3(2, 256), 256>>>(a2h, a2l, w2h, w2l, hb2, a3h, a3l, nullptr, 128, 128);
    hgemm_ps<false, false><<<dim3(1, 256), 256>>>(a3h, a3l, w3h, w3l, hb3, nullptr, nullptr, out, 64, 64);
}

// round 17
// speedup vs baseline: 1.2300x; 1.0497x over previous
#include <cuda_runtime.h>
#include <cuda_fp16.h>
#include <cstdint>
#include <cstddef>
#include <math.h>
#include <float.h>

#define NG   32
#define PTS  1024
#define NPT  (NG*PTS)      // 32768
#define KNB  30
#define DIM  64

// ---------------- device scratch (static, no allocations) ----------------
__device__ float g_s[NPT];
__device__ int   g_idx[NPT*KNB];
__device__ float g_B[NPT*DIM];
__device__ float g_C[NPT*DIM];
__device__ float g_hcat[NPT*192];
__device__ float g_big[(size_t)NPT*1024];   // dist (monotone uint); later a1 splits
__device__ float g_h1[NPT*256];             // later a2h/a2l
__device__ float g_h2[NPT*128];             // later a3h/a3l
__device__ unsigned g_w2h[64*32];
__device__ unsigned g_w2l[64*32];
__device__ unsigned g_x1h[NPT*8],  g_x1l[NPT*8];
__device__ unsigned g_ah0[NPT*96], g_al0[NPT*96];
__device__ unsigned g_wlh[1024*96],  g_wll[1024*96];
__device__ unsigned g_hw1h[256*512], g_hw1l[256*512];
__device__ unsigned g_hw2h[128*128], g_hw2l[128*128];
__device__ unsigned g_hw3h[64*64],   g_hw3l[64*64];

// ---------------- fp16 split helpers ----------------
__device__ __forceinline__ void split2(float x, float y, unsigned& h, unsigned& l) {
    __half2 p = __floats2half2_rn(x, y);
    h = *reinterpret_cast<unsigned*>(&p);
    float rx = x - __low2float(p);
    float ry = y - __high2float(p);
    __half2 q = __floats2half2_rn(rx, ry);
    l = *reinterpret_cast<unsigned*>(&q);
}
// order-preserving float -> uint map
__device__ __forceinline__ unsigned mapmono(float v) {
    int b = __float_as_int(v);
    return (unsigned)b ^ (0x80000000u | (unsigned)(b >> 31));
}

#define MMA_F16(d, a0,a1,a2,a3, b0,b1) \
    asm volatile("mma.sync.aligned.m16n8k16.row.col.f32.f16.f16.f32 " \
        "{%0,%1,%2,%3}, {%4,%5,%6,%7}, {%8,%9}, {%0,%1,%2,%3};" \
        : "+f"(d[0]),"+f"(d[1]),"+f"(d[2]),"+f"(d[3]) \
        : "r"(a0),"r"(a1),"r"(a2),"r"(a3), "r"(b0),"r"(b1))

// ---------------- prep kernels ----------------
__global__ void splitx1_k(const float* __restrict__ x) {
    int e = blockIdx.x*256 + threadIdx.x;
    int i = e >> 3, p = e & 7;
    float v0 = 0.f, v1 = 0.f;
    if (p < 7) { v0 = x[i*14 + 2*p]; v1 = x[i*14 + 2*p + 1]; }
    unsigned h, l; split2(v0, v1, h, l);
    g_x1h[e] = h; g_x1l[e] = l;
}

// coalesced transpose-split: W [K][N] fp32 -> Wh/Wl [N][KP] fp16-pair words.
__global__ void wprep_k(const float* __restrict__ W, unsigned* __restrict__ Wh,
                        unsigned* __restrict__ Wl, int K, int N) {
    __shared__ unsigned th[32][33], tl[32][33];
    int KP = K >> 1;
    int tp0 = blockIdx.x*32, tn0 = blockIdx.y*32;
    int tx = threadIdx.x & 31, ty4 = (threadIdx.x >> 5)*4;
    #pragma unroll
    for (int q = 0; q < 4; q++) {
        int p = tp0 + ty4 + q;
        float w0 = W[(size_t)(2*p)*N + tn0 + tx];
        float w1 = W[(size_t)(2*p + 1)*N + tn0 + tx];
        unsigned h, l; split2(w0, w1, h, l);
        th[ty4 + q][tx] = h;
        tl[ty4 + q][tx] = l;
    }
    __syncthreads();
    #pragma unroll
    for (int q = 0; q < 4; q++) {
        int n = tn0 + ty4 + q;
        Wh[(size_t)n*KP + tp0 + tx] = th[tx][ty4 + q];
        Wl[(size_t)n*KP + tp0 + tx] = tl[tx][ty4 + q];
    }
}

// ---------------- pairwise distances (pre-split fp16 3-term mma) --------------
// Epilogue stores MONOTONE-MAPPED uints (g_big is only read by topk).
template<int F>
__global__ void __launch_bounds__(256, 2) distmma_k(
        const unsigned* __restrict__ Xh, const unsigned* __restrict__ Xl,
        int strideP, int offP) {
    constexpr int PAIRS = ((F + 15)/16)*8;
    constexpr int STR   = PAIRS + 4;
    __shared__ unsigned Ah[128*STR], Al[128*STR];
    __shared__ unsigned Bh[64*STR],  Bl[64*STR];
    int g  = blockIdx.z;
    int bm = blockIdx.y*128, bn = blockIdx.x*64;
    int tid = threadIdx.x, lane = tid & 31, warp = tid >> 5;
    int wm = warp & 3, wn = warp >> 2;
    int gid = lane >> 2, tig = lane & 3;
    int base = g*PTS;

    for (int e = tid; e < 32*PAIRS; e += 256) {
        int r = e / (PAIRS/4), c4 = (e % (PAIRS/4))*4;
        size_t go = (size_t)(base + bm + r)*strideP + offP + c4;
        *(uint4*)&Ah[r*STR + c4] = *(const uint4*)&Xh[go];
        *(uint4*)&Al[r*STR + c4] = *(const uint4*)&Xl[go];
    }
    for (int e = tid; e < 16*PAIRS; e += 256) {
        int r = e / (PAIRS/4), c4 = (e % (PAIRS/4))*4;
        size_t go = (size_t)(base + bn + r)*strideP + offP + c4;
        *(uint4*)&Bh[r*STR + c4] = *(const uint4*)&Xh[go];
        *(uint4*)&Bl[r*STR + c4] = *(const uint4*)&Xl[go];
    }
    __syncthreads();

    float acc[2][4][4] = {};
    #pragma unroll
    for (int s = 0; s < PAIRS/8; s++) {
        int p = s*8 + tig;
        unsigned ah[2][4], al[2][4];
        #pragma unroll
        for (int mi = 0; mi < 2; mi++) {
            int r = wm*32 + mi*16 + gid;
            ah[mi][0] = Ah[r*STR + p];       ah[mi][1] = Ah[(r+8)*STR + p];
            ah[mi][2] = Ah[r*STR + p + 4];   ah[mi][3] = Ah[(r+8)*STR + p + 4];
            al[mi][0] = Al[r*STR + p];       al[mi][1] = Al[(r+8)*STR + p];
            al[mi][2] = Al[r*STR + p + 4];   al[mi][3] = Al[(r+8)*STR + p + 4];
        }
        #pragma unroll
        for (int ni = 0; ni < 4; ni++) {
            int c = wn*32 + ni*8 + gid;
            unsigned bh0 = Bh[c*STR + p], bh1 = Bh[c*STR + p + 4];
            unsigned bl0 = Bl[c*STR + p], bl1 = Bl[c*STR + p + 4];
            #pragma unroll
            for (int mi = 0; mi < 2; mi++) {
                MMA_F16(acc[mi][ni], ah[mi][0],ah[mi][1],ah[mi][2],ah[mi][3], bh0,bh1);
                MMA_F16(acc[mi][ni], ah[mi][0],ah[mi][1],ah[mi][2],ah[mi][3], bl0,bl1);
                MMA_F16(acc[mi][ni], al[mi][0],al[mi][1],al[mi][2],al[mi][3], bh0,bh1);
            }
        }
    }
    unsigned* bigU = (unsigned*)g_big;
    #pragma unroll
    for (int mi = 0; mi < 2; mi++) {
        int row = bm + wm*32 + mi*16 + gid;
        float si0 = g_s[base + row];
        float si1 = g_s[base + row + 8];
        #pragma unroll
        for (int ni = 0; ni < 4; ni++) {
            int col = bn + wn*32 + ni*8 + 2*tig;
            float sj0 = g_s[base + col];
            float sj1 = g_s[base + col + 1];
            uint2 o0, o1;
            o0.x = mapmono(si0 + sj0 - 2.f*acc[mi][ni][0]);
            o0.y = mapmono(si0 + sj1 - 2.f*acc[mi][ni][1]);
            o1.x = mapmono(si1 + sj0 - 2.f*acc[mi][ni][2]);
            o1.y = mapmono(si1 + sj1 - 2.f*acc[mi][ni][3]);
            *(uint2*)&bigU[(size_t)(base + row)*PTS + col]     = o0;
            *(uint2*)&bigU[(size_t)(base + row + 8)*PTS + col] = o1;
        }
    }
}

// ---------------- top-K selection (32-bit (d,t) top-3 cache; exact) -----------
// Consumption order is lexicographic (d, t, lane) == (d, point index j);
// rescans (rare) re-read the L2-hot global row. No smem, low regs.
__global__ void __launch_bounds__(256) topk_k() {
    int w = threadIdx.x >> 5, lane = threadIdx.x & 31;
    int i = blockIdx.x*8 + w;
    int g = i >> 10;
    const unsigned* row = (const unsigned*)&g_big[(size_t)i*PTS];

    unsigned d1 = 0xFFFFFFFFu, d2 = 0xFFFFFFFFu, d3 = 0xFFFFFFFFu;
    int t1 = 0, t2 = 0, t3 = 0;
    #pragma unroll
    for (int t = 0; t < 32; t++) {
        unsigned d = row[lane + 32*t];
        if (d < d1)      { d3 = d2; t3 = t2; d2 = d1; t2 = t1; d1 = d; t1 = t; }
        else if (d < d2) { d3 = d2; t3 = t2; d2 = d; t2 = t; }
        else if (d < d3) { d3 = d; t3 = t; }
    }
    unsigned lastd = 0; int lastt = -1;
    for (int kk = 0; kk < KNB; kk++) {
        unsigned umin = __reduce_min_sync(0xffffffffu, d1);
        unsigned myjv = (d1 == umin) ? (unsigned)(lane + 32*t1) : 0xFFFFFFFFu;
        unsigned jv = __reduce_min_sync(0xffffffffu, myjv);
        if (lane == 0) g_idx[(size_t)i*KNB + kk] = (g << 10) + (int)jv;
        if ((jv & 31) == lane) {
            lastd = d1; lastt = t1;
            d1 = d2; t1 = t2; d2 = d3; t2 = t3; d3 = 0xFFFFFFFFu;
            if (d1 == 0xFFFFFFFFu) {            // cache drained: rescan > (lastd,lastt)
                d2 = 0xFFFFFFFFu; d3 = 0xFFFFFFFFu;
                #pragma unroll 4
                for (int t = 0; t < 32; t++) {
                    unsigned d = row[lane + 32*t];
                    if (d > lastd || (d == lastd && t > lastt)) {
                        if (d < d1)      { d3 = d2; t3 = t2; d2 = d1; t2 = t1; d1 = d; t1 = t; }
                        else if (d < d2) { d3 = d2; t3 = t2; d2 = d; t2 = t; }
                        else if (d < d3) { d3 = d; t3 = t; }
                    }
                }
            }
        }
    }
}

// ---------------- precompute B/C (+ squared norms fused) ----------------
template<int F>
__global__ void precompute_k(const float* __restrict__ x, int ldx,
                             const float* __restrict__ W1, const float* __restrict__ b1) {
    int gid = blockIdx.x*256 + threadIdx.x;
    int i = gid >> 6, c = gid & 63;
    const float* xr = x + (size_t)i*ldx;
    float a = 0.f, b = 0.f, s = 0.f;
    #pragma unroll
    for (int f = 0; f < F; f++) {
        float xv = xr[f];
        a += xv * W1[f*DIM + c];
        b += xv * W1[(F + f)*DIM + c];
        s += xv * xv;
    }
    g_B[gid] = b;
    g_C[gid] = a - b + b1[c];
    if (c == 0) g_s[i] = s;
}

// ---------------- edgeconv W2 prep ----------------
__global__ void w2prep_k(const float* __restrict__ W2) {
    int e = blockIdx.x*256 + threadIdx.x;
    int n = e & 63, j = e >> 6;
    float w0 = W2[(2*j)*64 + n];
    float w1 = W2[(2*j+1)*64 + n];
    unsigned h, l; split2(w0, w1, h, l);
    g_w2h[n*32 + j] = h;
    g_w2l[n*32 + j] = l;
}

// ---------------- edgeconv ----------------
template<bool AL, bool SPLITLO>
__global__ void __launch_bounds__(128) edgeconv_k(
        const float* __restrict__ b2, float* __restrict__ out, int ldo,
        unsigned* __restrict__ oh, unsigned* __restrict__ ol) {
    __shared__ unsigned Hh[4][32][36];
    __shared__ unsigned Hl[4][32][36];
    int tid = threadIdx.x, lane = tid & 31, warp = tid >> 5;
    int gid = lane >> 2, tig = lane & 3;
    int i = blockIdx.x*4 + warp;

    unsigned (*hh)[36] = Hh[warp];
    unsigned (*hl)[36] = Hl[warp];
    const int* idxr = g_idx + (size_t)i*KNB;
    float2 cv = *(const float2*)&g_C[(size_t)i*DIM + 2*lane];
    #pragma unroll
    for (int k = 0; k < 32; k++) {
        int j = idxr[(k < KNB) ? k : 0];
        float2 bv = *(const float2*)&g_B[(size_t)j*DIM + 2*lane];
        float f0 = fmaxf(cv.x + bv.x, 0.f);
        float f1 = fmaxf(cv.y + bv.y, 0.f);
        unsigned h, l; split2(f0, f1, h, l);
        hh[k][lane] = h;
        if (AL) hl[k][lane] = l;
    }
    __syncwarp();

    float acc[2][8][4] = {};
    #pragma unroll
    for (int s = 0; s < 4; s++) {
        int p = s*8 + tig;
        unsigned ah[2][4], al[2][4];
        #pragma unroll
        for (int mi = 0; mi < 2; mi++) {
            int r = mi*16 + gid;
            ah[mi][0] = hh[r][p];   ah[mi][1] = hh[r+8][p];
            ah[mi][2] = hh[r][p+4]; ah[mi][3] = hh[r+8][p+4];
            if (AL) {
                al[mi][0] = hl[r][p];   al[mi][1] = hl[r+8][p];
                al[mi][2] = hl[r][p+4]; al[mi][3] = hl[r+8][p+4];
            }
        }
        #pragma unroll
        for (int ni = 0; ni < 8; ni++) {
            int c = ni*8 + gid;
            unsigned bh0 = g_w2h[c*32 + p], bh1 = g_w2h[c*32 + p + 4];
            unsigned bl0 = g_w2l[c*32 + p], bl1 = g_w2l[c*32 + p + 4];
            #pragma unroll
            for (int mi = 0; mi < 2; mi++) {
                MMA_F16(acc[mi][ni], ah[mi][0],ah[mi][1],ah[mi][2],ah[mi][3], bh0,bh1);
                MMA_F16(acc[mi][ni], ah[mi][0],ah[mi][1],ah[mi][2],ah[mi][3], bl0,bl1);
                if (AL)
                    MMA_F16(acc[mi][ni], al[mi][0],al[mi][1],al[mi][2],al[mi][3], bh0,bh1);
            }
        }
    }
    #pragma unroll
    for (int ni = 0; ni < 8; ni++) {
        float m0 = fmaxf(fmaxf(acc[0][ni][0], acc[0][ni][2]),
                         fmaxf(acc[1][ni][0], acc[1][ni][2]));
        float m1 = fmaxf(fmaxf(acc[0][ni][1], acc[0][ni][3]),
                         fmaxf(acc[1][ni][1], acc[1][ni][3]));
        m0 = fmaxf(m0, __shfl_xor_sync(0xffffffffu, m0, 4));
        m1 = fmaxf(m1, __shfl_xor_sync(0xffffffffu, m1, 4));
        m0 = fmaxf(m0, __shfl_xor_sync(0xffffffffu, m0, 8));
        m1 = fmaxf(m1, __shfl_xor_sync(0xffffffffu, m1, 8));
        m0 = fmaxf(m0, __shfl_xor_sync(0xffffffffu, m0, 16));
        m1 = fmaxf(m1, __shfl_xor_sync(0xffffffffu, m1, 16));
        if (gid == 0) {
            int col = ni*8 + tig*2;
            float2 bz = *(const float2*)&b2[col];
            float o0 = fmaxf(m0 + bz.x, 0.f);
            float o1 = fmaxf(m1 + bz.y, 0.f);
            *(float2*)&out[(size_t)i*ldo + col] = make_float2(o0, o1);
            unsigned h, l; split2(o0, o1, h, l);
            oh[(size_t)i*96 + (col >> 1)] = h;
            if (SPLITLO) ol[(size_t)i*96 + (col >> 1)] = l;
        }
    }
}

// ---------------- wide-M pre-split GEMM with internal N loop ----------------
template<bool SPLITLO, int NT>
__global__ void __launch_bounds__(256, 2) hgemm_w(
        const unsigned* __restrict__ Ah_g,
        const unsigned* __restrict__ Wh_g, const unsigned* __restrict__ Wl_g,
        const float* __restrict__ bias,
        unsigned* __restrict__ Oh, unsigned* __restrict__ Ol,
        int KP, int Nd) {
    __shared__ unsigned Ahs[256*20];
    __shared__ unsigned Bhs[64*20], Bls[64*20];
    int tid  = threadIdx.x;
    int lane = tid & 31, warp = tid >> 5;
    int wm = warp & 3, wn = warp >> 2;
    int gid = lane >> 2, tig = lane & 3;
    int bm = blockIdx.y * 256;
    int NdP = Nd >> 1;

    #pragma unroll 1
    for (int nt = 0; nt < NT; nt++) {
        int bn = (blockIdx.x*NT + nt)*64;
        float acc[4][4][4] = {};
        #pragma unroll 1
        for (int k0p = 0; k0p < KP; k0p += 16) {
            uint4 ra[4], rbh, rbl;
            #pragma unroll
            for (int q = 0; q < 4; q++) {
                int e = q*256 + tid;
                int r = e >> 2, c4 = (e & 3)*4;
                ra[q] = *(const uint4*)&Ah_g[(size_t)(bm + r)*KP + k0p + c4];
            }
            {
                int r = tid >> 2, c4 = (tid & 3)*4;
                size_t go = (size_t)(bn + r)*KP + k0p + c4;
                rbh = *(const uint4*)&Wh_g[go];
                rbl = *(const uint4*)&Wl_g[go];
            }
            __syncthreads();
            #pragma unroll
            for (int q = 0; q < 4; q++) {
                int e = q*256 + tid;
                int r = e >> 2, c4 = (e & 3)*4;
                *(uint4*)&Ahs[r*20 + c4] = ra[q];
            }
            {
                int r = tid >> 2, c4 = (tid & 3)*4;
                *(uint4*)&Bhs[r*20 + c4] = rbh;
                *(uint4*)&Bls[r*20 + c4] = rbl;
            }
            __syncthreads();
            #pragma unroll
            for (int s = 0; s < 2; s++) {
                int p = s*8 + tig;
                unsigned ah[4][4];
                #pragma unroll
                for (int mi = 0; mi < 4; mi++) {
                    int r = wm*64 + mi*16 + gid;
                    ah[mi][0] = Ahs[r*20 + p];       ah[mi][1] = Ahs[(r+8)*20 + p];
                    ah[mi][2] = Ahs[r*20 + p + 4];   ah[mi][3] = Ahs[(r+8)*20 + p + 4];
                }
                #pragma unroll
                for (int ni = 0; ni < 4; ni++) {
                    int c = wn*32 + ni*8 + gid;
                    unsigned bh0 = Bhs[c*20 + p], bh1 = Bhs[c*20 + p + 4];
                    unsigned bl0 = Bls[c*20 + p], bl1 = Bls[c*20 + p + 4];
                    #pragma unroll
                    for (int mi = 0; mi < 4; mi++) {
                        MMA_F16(acc[mi][ni], ah[mi][0],ah[mi][1],ah[mi][2],ah[mi][3], bh0,bh1);
                        MMA_F16(acc[mi][ni], ah[mi][0],ah[mi][1],ah[mi][2],ah[mi][3], bl0,bl1);
                    }
                }
            }
        }
        #pragma unroll
        for (int mi = 0; mi < 4; mi++) {
            int row = bm + wm*64 + mi*16 + gid;
            #pragma unroll
            for (int ni = 0; ni < 4; ni++) {
                int col = bn + wn*32 + ni*8 + tig*2;
                float bz0 = bias[col], bz1 = bias[col+1];
                float z0 = fmaxf(acc[mi][ni][0] + bz0, 0.f);
                float z1 = fmaxf(acc[mi][ni][1] + bz1, 0.f);
                float z2 = fmaxf(acc[mi][ni][2] + bz0, 0.f);
                float z3 = fmaxf(acc[mi][ni][3] + bz1, 0.f);
                unsigned h, l;
                split2(z0, z1, h, l);
                Oh[(size_t)row*NdP + (col >> 1)] = h;
                if (SPLITLO) Ol[(size_t)row*NdP + (col >> 1)] = l;
                split2(z2, z3, h, l);
                Oh[(size_t)(row+8)*NdP + (col >> 1)] = h;
                if (SPLITLO) Ol[(size_t)(row+8)*NdP + (col >> 1)] = l;
            }
        }
    }
}

// ---------------- pre-split fp16 GEMM (3-term, small layers) ----------------
template<bool RELU, bool SPLITOUT>
__global__ void __launch_bounds__(256, 2) hgemm_ps(
        const unsigned* __restrict__ Ah_g, const unsigned* __restrict__ Al_g,
        const unsigned* __restrict__ Wh_g, const unsigned* __restrict__ Wl_g,
        const float* __restrict__ bias,
        unsigned* __restrict__ Oh, unsigned* __restrict__ Ol,
        float* __restrict__ Of, int KP, int Nd) {
    __shared__ unsigned Ahs[128*20], Als[128*20];
    __shared__ unsigned Bhs[64*20],  Bls[64*20];
    int tid  = threadIdx.x;
    int lane = tid & 31, warp = tid >> 5;
    int wm = warp & 3, wn = warp >> 2;
    int gid = lane >> 2, tig = lane & 3;
    int bm = blockIdx.y * 128, bn = blockIdx.x * 64;
    float acc[2][4][4] = {};

    for (int k0p = 0; k0p < KP; k0p += 16) {
        uint4 rah[2], ral[2], rbh, rbl;
        #pragma unroll
        for (int q = 0; q < 2; q++) {
            int e = q*256 + tid;
            int r = e >> 2, c4 = (e & 3)*4;
            size_t go = (size_t)(bm + r)*KP + k0p + c4;
            rah[q] = *(const uint4*)&Ah_g[go];
            ral[q] = *(const uint4*)&Al_g[go];
        }
        {
            int r = tid >> 2, c4 = (tid & 3)*4;
            size_t go = (size_t)(bn + r)*KP + k0p + c4;
            rbh = *(const uint4*)&Wh_g[go];
            rbl = *(const uint4*)&Wl_g[go];
        }
        __syncthreads();
        #pragma unroll
        for (int q = 0; q < 2; q++) {
            int e = q*256 + tid;
            int r = e >> 2, c4 = (e & 3)*4;
            *(uint4*)&Ahs[r*20 + c4] = rah[q];
            *(uint4*)&Als[r*20 + c4] = ral[q];
        }
        {
            int r = tid >> 2, c4 = (tid & 3)*4;
            *(uint4*)&Bhs[r*20 + c4] = rbh;
            *(uint4*)&Bls[r*20 + c4] = rbl;
        }
        __syncthreads();
        #pragma unroll
        for (int s = 0; s < 2; s++) {
            int p = s*8 + tig;
            unsigned ah[2][4], al[2][4];
            #pragma unroll
            for (int mi = 0; mi < 2; mi++) {
                int r = wm*32 + mi*16 + gid;
                ah[mi][0] = Ahs[r*20 + p];       ah[mi][1] = Ahs[(r+8)*20 + p];
                ah[mi][2] = Ahs[r*20 + p + 4];   ah[mi][3] = Ahs[(r+8)*20 + p + 4];
                al[mi][0] = Als[r*20 + p];       al[mi][1] = Als[(r+8)*20 + p];
                al[mi][2] = Als[r*20 + p + 4];   al[mi][3] = Als[(r+8)*20 + p + 4];
            }
            #pragma unroll
            for (int ni = 0; ni < 4; ni++) {
                int c = wn*32 + ni*8 + gid;
                unsigned bh0 = Bhs[c*20 + p], bh1 = Bhs[c*20 + p + 4];
                unsigned bl0 = Bls[c*20 + p], bl1 = Bls[c*20 + p + 4];
                #pragma unroll
                for (int mi = 0; mi < 2; mi++) {
                    MMA_F16(acc[mi][ni], ah[mi][0],ah[mi][1],ah[mi][2],ah[mi][3], bh0,bh1);
                    MMA_F16(acc[mi][ni], ah[mi][0],ah[mi][1],ah[mi][2],ah[mi][3], bl0,bl1);
                    MMA_F16(acc[mi][ni], al[mi][0],al[mi][1],al[mi][2],al[mi][3], bh0,bh1);
                }
            }
        }
    }
    int NdP = Nd >> 1;
    #pragma unroll
    for (int mi = 0; mi < 2; mi++) {
        int row = bm + wm*32 + mi*16 + gid;
        #pragma unroll
        for (int ni = 0; ni < 4; ni++) {
            int col = bn + wn*32 + ni*8 + tig*2;
            float bz0 = bias[col], bz1 = bias[col+1];
            float z0 = acc[mi][ni][0] + bz0;
            float z1 = acc[mi][ni][1] + bz1;
            float z2 = acc[mi][ni][2] + bz0;
            float z3 = acc[mi][ni][3] + bz1;
            if (RELU) {
                z0 = fmaxf(z0, 0.f); z1 = fmaxf(z1, 0.f);
                z2 = fmaxf(z2, 0.f); z3 = fmaxf(z3, 0.f);
            }
            if (SPLITOUT) {
                unsigned h, l;
                split2(z0, z1, h, l);
                Oh[(size_t)row*NdP + (col >> 1)] = h;
                Ol[(size_t)row*NdP + (col >> 1)] = l;
                split2(z2, z3, h, l);
                Oh[(size_t)(row+8)*NdP + (col >> 1)] = h;
                Ol[(size_t)(row+8)*NdP + (col >> 1)] = l;
            } else {
                *(float2*)&Of[(size_t)row*Nd + col]     = make_float2(z0, z1);
                *(float2*)&Of[(size_t)(row+8)*Nd + col] = make_float2(z2, z3);
            }
        }
    }
}

// ---------------- host orchestration ----------------
template<int F, bool EAL>
static void run_conv(const float* xp, int ldx,
                     const unsigned* xh, const unsigned* xl, int strideP, int offP,
                     const float* w1, const float* b1,
                     const float* w2, const float* b2,
                     float* outp, unsigned* oh, unsigned* ol) {
    precompute_k<F><<<(NPT*DIM)/256, 256>>>(xp, ldx, w1, b1);
    distmma_k<F><<<dim3(PTS/64, PTS/128, NG), 256>>>(xh, xl, strideP, offP);
    topk_k<<<NPT/8, 256>>>();
    w2prep_k<<<8, 256>>>(w2);
    edgeconv_k<EAL, EAL><<<NPT/4, 128>>>(b2, outp, 192, oh, ol);
}

extern "C" void kernel_launch(void* const* d_in, const int* in_sizes, int n_in,
                              void* d_out, int out_size) {
    const float* x    = (const float*)d_in[0];
    const float* c1w1 = (const float*)d_in[2];
    const float* c1b1 = (const float*)d_in[3];
    const float* c1w2 = (const float*)d_in[4];
    const float* c1b2 = (const float*)d_in[5];
    const float* c2w1 = (const float*)d_in[6];
    const float* c2b1 = (const float*)d_in[7];
    const float* c2w2 = (const float*)d_in[8];
    const float* c2b2 = (const float*)d_in[9];
    const float* c3w1 = (const float*)d_in[10];
    const float* c3b1 = (const float*)d_in[11];
    const float* c3w2 = (const float*)d_in[12];
    const float* c3b2 = (const float*)d_in[13];
    const float* lw   = (const float*)d_in[14];
    const float* lb   = (const float*)d_in[15];
    const float* hw1  = (const float*)d_in[16];
    const float* hb1  = (const float*)d_in[17];
    const float* hw2  = (const float*)d_in[18];
    const float* hb2  = (const float*)d_in[19];
    const float* hw3  = (const float*)d_in[20];
    const float* hb3  = (const float*)d_in[21];
    float* out = (float*)d_out;

    float *hcat, *big, *h1b, *h2b;
    unsigned *x1h, *x1l, *ah0, *al0;
    unsigned *wlh, *wll, *w1h, *w1l, *w2h, *w2l, *w3h, *w3l;
    cudaGetSymbolAddress((void**)&hcat, g_hcat);
    cudaGetSymbolAddress((void**)&big,  g_big);
    cudaGetSymbolAddress((void**)&h1b,  g_h1);
    cudaGetSymbolAddress((void**)&h2b,  g_h2);
    cudaGetSymbolAddress((void**)&x1h,  g_x1h);
    cudaGetSymbolAddress((void**)&x1l,  g_x1l);
    cudaGetSymbolAddress((void**)&ah0,  g_ah0);
    cudaGetSymbolAddress((void**)&al0,  g_al0);
    cudaGetSymbolAddress((void**)&wlh,  g_wlh);
    cudaGetSymbolAddress((void**)&wll,  g_wll);
    cudaGetSymbolAddress((void**)&w1h,  g_hw1h);
    cudaGetSymbolAddress((void**)&w1l,  g_hw1l);
    cudaGetSymbolAddress((void**)&w2h,  g_hw2h);
    cudaGetSymbolAddress((void**)&w2l,  g_hw2l);
    cudaGetSymbolAddress((void**)&w3h,  g_hw3h);
    cudaGetSymbolAddress((void**)&w3l,  g_hw3l);

    unsigned* a1h = (unsigned*)big;  unsigned* a1l = a1h + (size_t)NPT*512;
    unsigned* a2h = (unsigned*)h1b;  unsigned* a2l = a2h + (size_t)NPT*128;
    unsigned* a3h = (unsigned*)h2b;  unsigned* a3l = a3h + (size_t)NPT*64;

    splitx1_k<<<(NPT*8)/256, 256>>>(x);

    run_conv<14, true >(x,         14,  x1h, x1l, 8,  0,  c1w1, c1b1, c1w2, c1b2,
                        hcat,       ah0,      al0);
    run_conv<64, true >(hcat,      192, ah0, al0, 96, 0,  c2w1, c2b1, c2w2, c2b2,
                        hcat + 64,  ah0 + 32, al0 + 32);
    run_conv<64, false>(hcat + 64, 192, ah0, al0, 96, 32, c3w1, c3b1, c3w2, c3b2,
                        hcat + 128, ah0 + 64, al0 + 64);

    // coalesced weight prep (32x32 smem transpose tiles)
    wprep_k<<<dim3(96/32,  1024/32), 256>>>(lw,  wlh, wll, 192,  1024);
    wprep_k<<<dim3(512/32, 256/32),  256>>>(hw1, w1h, w1l, 1024, 256);
    wprep_k<<<dim3(128/32, 128/32),  256>>>(hw2, w2h, w2l, 256,  128);
    wprep_k<<<dim3(64/32,  64/32),   256>>>(hw3, w3h, w3l, 128,  64);

    hgemm_w<false, 4><<<dim3(4, 128), 256>>>(ah0, wlh, wll, lb,  a1h, nullptr, 96,  1024);
    hgemm_w<true,  2><<<dim3(2, 128), 256>>>(a1h, w1h, w1l, hb1, a2h, a2l,     512, 256);
    hgemm_ps<true,  true ><<<dim3(2, 256), 256>>>(a2h, a2l, w2h, w2l, hb2, a3h, a3l, nullptr, 128, 128);
    hgemm_ps<false, false><<<dim3(1, 256), 256>>>(a3h, a3l, w3h, w3l, hb3, nullptr, nullptr, out, 64, 64);
}